// round 3
// baseline (speedup 1.0000x reference)
#include <cuda_runtime.h>
#define B_ 2
#define S_ 2048
#define D_ 1024
#define H_ 16
typedef unsigned long long u64;

__device__ float g_Q[B_*S_*D_], g_K[B_*S_*D_], g_V[B_*S_*D_], g_C[B_*S_*D_];

__device__ __forceinline__ u64 dup2(float x){u64 r;asm("mov.b64 %0,{%1,%1};":"=l"(r):"f"(x));return r;}
__device__ __forceinline__ void fma2(u64&d,u64 a,u64 b){asm("fma.rn.f32x2 %0,%1,%2,%0;":"+l"(d):"l"(a),"l"(b));}
__device__ __forceinline__ void mul2(u64&d,u64 a){asm("mul.rn.f32x2 %0,%0,%1;":"+l"(d):"l"(a));}
__device__ __forceinline__ float2 up2(u64 v){float2 r;asm("mov.b64 {%0,%1},%2;":"=f"(r.x),"=f"(r.y):"l"(v));return r;}

// 64x64 tile, BK=8, 64 threads, 8x8/thread, f32x2, double-buffered smem.
__global__ void __launch_bounds__(64)
proj_kernel(const float* __restrict__ X, const float* __restrict__ W,
            const float* __restrict__ bias, float* __restrict__ out)
{
    __shared__ __align__(16) float Xs[2][8][68], Ws[2][8][68];
    const int t = threadIdx.x, tx = t & 7, ty = t >> 3;
    const int bm = blockIdx.y * 64, bn = blockIdx.x * 64;
    const int pr = t + ((t >> 5) & 1) * 4;                 // swizzled store col
    const int kb = tx * 8 + ((tx >> 2) & 1) * 4;           // b-frag base
    const int ab = ty * 8 + ((ty >> 2) & 1) * 4;           // a-frag base

    const float* xp = X + (size_t)(bm + t) * D_;
    const float* wp = W + (size_t)(bn + t) * D_;
    float4 xv0 = *(const float4*)xp, xv1 = *(const float4*)(xp + 4);
    float4 wv0 = *(const float4*)wp, wv1 = *(const float4*)(wp + 4);
    u64 acc[8][4] = {};

    for (int k0 = 0; k0 < D_; k0 += 8) {
        int bf = (k0 >> 3) & 1;
        Xs[bf][0][pr]=xv0.x; Xs[bf][1][pr]=xv0.y; Xs[bf][2][pr]=xv0.z; Xs[bf][3][pr]=xv0.w;
        Xs[bf][4][pr]=xv1.x; Xs[bf][5][pr]=xv1.y; Xs[bf][6][pr]=xv1.z; Xs[bf][7][pr]=xv1.w;
        Ws[bf][0][pr]=wv0.x; Ws[bf][1][pr]=wv0.y; Ws[bf][2][pr]=wv0.z; Ws[bf][3][pr]=wv0.w;
        Ws[bf][4][pr]=wv1.x; Ws[bf][5][pr]=wv1.y; Ws[bf][6][pr]=wv1.z; Ws[bf][7][pr]=wv1.w;
        __syncthreads();
        if (k0 + 8 < D_) {
            xp += 8; wp += 8;
            xv0 = *(const float4*)xp; xv1 = *(const float4*)(xp + 4);
            wv0 = *(const float4*)wp; wv1 = *(const float4*)(wp + 4);
        }
        #pragma unroll
        for (int kk = 0; kk < 8; kk++) {
            float4 a0 = *(const float4*)&Xs[bf][kk][ab];
            float4 a1 = *(const float4*)&Xs[bf][kk][ab + 4];
            ulonglong2 b0 = *(const ulonglong2*)&Ws[bf][kk][kb];
            ulonglong2 b1 = *(const ulonglong2*)&Ws[bf][kk][kb + 4];
            float av[8] = {a0.x,a0.y,a0.z,a0.w,a1.x,a1.y,a1.z,a1.w};
            #pragma unroll
            for (int i = 0; i < 8; i++) {
                u64 A = dup2(av[i]);
                fma2(acc[i][0],A,b0.x); fma2(acc[i][1],A,b0.y);
                fma2(acc[i][2],A,b1.x); fma2(acc[i][3],A,b1.y);
            }
        }
        // one sync/iter: stores at iter i+2 (same buf) can't pass the sync at
        // iter i+1, which follows compute(i) on every thread.
    }
    float4 bb0 = *(const float4*)&bias[bn + tx * 8];
    float4 bb1 = *(const float4*)&bias[bn + tx * 8 + 4];
    #pragma unroll
    for (int i = 0; i < 8; i++) {
        size_t base = (size_t)(bm + ty * 8 + i) * D_ + bn + tx * 8;
        float2 e0=up2(acc[i][0]), e1=up2(acc[i][1]), e2=up2(acc[i][2]), e3=up2(acc[i][3]);
        *(float4*)&out[base]   = make_float4(e0.x+bb0.x, e0.y+bb0.y, e1.x+bb0.z, e1.y+bb0.w);
        *(float4*)&out[base+4] = make_float4(e2.x+bb1.x, e2.y+bb1.y, e3.x+bb1.z, e3.y+bb1.w);
    }
}

// Flash attention: 64 threads, q-tile 64, k-tile 64, 8x8/thread both GEMMs.
__global__ void __launch_bounds__(64)
attn_kernel(const float* __restrict__ Q, const float* __restrict__ K,
            const float* __restrict__ V, const int* __restrict__ mask,
            float* __restrict__ ctx)
{
    extern __shared__ float sm[];
    float (*QsT)[68] = (float(*)[68])sm;                 // [d][q]
    float (*KsT)[68] = (float(*)[68])(sm + 64*68);       // [d][k] swizzled
    float (*Vs )[68] = (float(*)[68])(sm + 2*64*68);     // [k][d] swizzled
    float (*PsT)[68] = (float(*)[68])(sm + 3*64*68);     // [k][q] slot-swizzled

    const int t = threadIdx.x, tk = t & 7, tq = t >> 3;
    const int b = blockIdx.z, h = blockIdx.y, q0 = blockIdx.x * 64;
    const int pk = t + ((t >> 5) & 1) * 4;
    const int kb = tk * 8 + ((tk >> 2) & 1) * 4;
    const int sl = tq ^ tk;
    const int ps = sl * 8 + ((sl >> 2) & 1) * 4;

    {   // Q transposed, scale folded
        const float* qg = Q + (size_t)(b * S_ + q0 + t) * D_ + h * 64;
        #pragma unroll
        for (int c = 0; c < 16; c++) {
            float4 v = *(const float4*)(qg + c * 4);
            QsT[4*c+0][t]=v.x*.125f; QsT[4*c+1][t]=v.y*.125f;
            QsT[4*c+2][t]=v.z*.125f; QsT[4*c+3][t]=v.w*.125f;
        }
    }
    u64 o2[8][4] = {};
    float m_i[8], l_i[8];
    #pragma unroll
    for (int i = 0; i < 8; i++) { m_i[i] = -1e30f; l_i[i] = 0.f; }

    for (int k0 = 0; k0 < S_; k0 += 64) {
        const float* kg = K + (size_t)(b * S_ + k0 + t) * D_ + h * 64;
        const float* vg = V + (size_t)(b * S_ + k0 + t) * D_ + h * 64;
        #pragma unroll
        for (int c = 0; c < 16; c++) {
            float4 kv = *(const float4*)(kg + c * 4);
            KsT[4*c+0][pk]=kv.x; KsT[4*c+1][pk]=kv.y;
            KsT[4*c+2][pk]=kv.z; KsT[4*c+3][pk]=kv.w;
            int c4 = c * 4, pc = c4 + ((c4 >> 5) & 1) * 4;
            *(float4*)&Vs[t][pc] = *(const float4*)(vg + c4);
        }
        __syncthreads();

        u64 s2[8][4] = {};
        #pragma unroll 8
        for (int d = 0; d < 64; d++) {
            float4 a0 = *(const float4*)&QsT[d][tq * 8];
            float4 a1 = *(const float4*)&QsT[d][tq * 8 + 4];
            ulonglong2 b0 = *(const ulonglong2*)&KsT[d][kb];
            ulonglong2 b1 = *(const ulonglong2*)&KsT[d][kb + 4];
            float av[8] = {a0.x,a0.y,a0.z,a0.w,a1.x,a1.y,a1.z,a1.w};
            #pragma unroll
            for (int i = 0; i < 8; i++) {
                u64 A = dup2(av[i]);
                fma2(s2[i][0],A,b0.x); fma2(s2[i][1],A,b0.y);
                fma2(s2[i][2],A,b1.x); fma2(s2[i][3],A,b1.y);
            }
        }

        const int* mp = mask + (size_t)(q0 + tq * 8) * S_ + k0 + tk * 8;
        #pragma unroll
        for (int i = 0; i < 8; i++) {
            float2 e0=up2(s2[i][0]), e1=up2(s2[i][1]), e2=up2(s2[i][2]), e3=up2(s2[i][3]);
            float p[8] = {e0.x,e0.y,e1.x,e1.y,e2.x,e2.y,e3.x,e3.y};
            int4 m0 = *(const int4*)(mp + (size_t)i * S_);
            int4 m1 = *(const int4*)(mp + (size_t)i * S_ + 4);
            if(m0.x==0)p[0]=-1e9f; if(m0.y==0)p[1]=-1e9f;
            if(m0.z==0)p[2]=-1e9f; if(m0.w==0)p[3]=-1e9f;
            if(m1.x==0)p[4]=-1e9f; if(m1.y==0)p[5]=-1e9f;
            if(m1.z==0)p[6]=-1e9f; if(m1.w==0)p[7]=-1e9f;
            float rm = p[0];
            #pragma unroll
            for (int j = 1; j < 8; j++) rm = fmaxf(rm, p[j]);
            rm = fmaxf(rm, __shfl_xor_sync(0xffffffffu, rm, 1));
            rm = fmaxf(rm, __shfl_xor_sync(0xffffffffu, rm, 2));
            rm = fmaxf(rm, __shfl_xor_sync(0xffffffffu, rm, 4));
            float mn = fmaxf(m_i[i], rm);
            float al = __expf(m_i[i] - mn);
            float rs = 0.f;
            #pragma unroll
            for (int j = 0; j < 8; j++) { p[j] = __expf(p[j] - mn); rs += p[j]; }
            rs += __shfl_xor_sync(0xffffffffu, rs, 1);
            rs += __shfl_xor_sync(0xffffffffu, rs, 2);
            rs += __shfl_xor_sync(0xffffffffu, rs, 4);
            l_i[i] = l_i[i] * al + rs; m_i[i] = mn;
            u64 A = dup2(al);
            mul2(o2[i][0],A); mul2(o2[i][1],A); mul2(o2[i][2],A); mul2(o2[i][3],A);
            #pragma unroll
            for (int j = 0; j < 8; j++) PsT[tk * 8 + j][ps + i] = p[j];
        }
        __syncthreads();

        #pragma unroll 8
        for (int kk = 0; kk < 64; kk++) {
            int so = tq ^ (kk >> 3);
            int pb = so * 8 + ((so >> 2) & 1) * 4;
            float4 a0 = *(const float4*)&PsT[kk][pb];
            float4 a1 = *(const float4*)&PsT[kk][pb + 4];
            ulonglong2 b0 = *(const ulonglong2*)&Vs[kk][kb];
            ulonglong2 b1 = *(const ulonglong2*)&Vs[kk][kb + 4];
            float av[8] = {a0.x,a0.y,a0.z,a0.w,a1.x,a1.y,a1.z,a1.w};
            #pragma unroll
            for (int i = 0; i < 8; i++) {
                u64 A = dup2(av[i]);
                fma2(o2[i][0],A,b0.x); fma2(o2[i][1],A,b0.y);
                fma2(o2[i][2],A,b1.x); fma2(o2[i][3],A,b1.y);
            }
        }
        __syncthreads();
    }
    #pragma unroll
    for (int i = 0; i < 8; i++) {
        float inv = 1.f / l_i[i];
        float2 e0=up2(o2[i][0]), e1=up2(o2[i][1]), e2=up2(o2[i][2]), e3=up2(o2[i][3]);
        size_t base = (size_t)(b * S_ + q0 + tq * 8 + i) * D_ + h * 64 + tk * 8;
        *(float4*)&ctx[base]   = make_float4(e0.x*inv, e0.y*inv, e1.x*inv, e1.y*inv);
        *(float4*)&ctx[base+4] = make_float4(e2.x*inv, e2.y*inv, e3.x*inv, e3.y*inv);
    }
}

extern "C" void kernel_launch(void* const* d_in, const int* in_sizes, int n_in,
                              void* d_out, int out_size)
{
    const float* q  = (const float*)d_in[0];
    const float* k  = (const float*)d_in[1];
    const float* v  = (const float*)d_in[2];
    const int* mask = (const int*)  d_in[3];
    const float* Wq = (const float*)d_in[4];  const float* bq = (const float*)d_in[5];
    const float* Wk = (const float*)d_in[6];  const float* bk = (const float*)d_in[7];
    const float* Wv = (const float*)d_in[8];  const float* bv = (const float*)d_in[9];
    const float* Wo = (const float*)d_in[10]; const float* bo = (const float*)d_in[11];
    float* out = (float*)d_out;

    float *Qp, *Kp, *Vp, *Cp;
    cudaGetSymbolAddress((void**)&Qp, g_Q);
    cudaGetSymbolAddress((void**)&Kp, g_K);
    cudaGetSymbolAddress((void**)&Vp, g_V);
    cudaGetSymbolAddress((void**)&Cp, g_C);

    dim3 pg(D_ / 64, (B_ * S_) / 64);   // 16 x 64 = 1024 CTAs
    proj_kernel<<<pg, 64>>>(q, Wq, bq, Qp);
    proj_kernel<<<pg, 64>>>(k, Wk, bk, Kp);
    proj_kernel<<<pg, 64>>>(v, Wv, bv, Vp);

    const int asmem = 4 * 64 * 68 * (int)sizeof(float);  // 69632 B
    cudaFuncSetAttribute(attn_kernel, cudaFuncAttributeMaxDynamicSharedMemorySize, asmem);
    attn_kernel<<<dim3(S_ / 64, H_, B_), 64, asmem>>>(Qp, Kp, Vp, mask, Cp);

    proj_kernel<<<pg, 64>>>(Cp, Wo, bo, out);
}

// round 4
// speedup vs baseline: 1.2062x; 1.2062x over previous
#include <cuda_runtime.h>
#define B_ 2
#define S_ 2048
#define D_ 1024
#define H_ 16
typedef unsigned long long u64;

__device__ float g_Q[B_*S_*D_], g_K[B_*S_*D_], g_V[B_*S_*D_], g_C[B_*S_*D_];

__device__ __forceinline__ u64 dup2(float x){u64 r;asm("mov.b64 %0,{%1,%1};":"=l"(r):"f"(x));return r;}
__device__ __forceinline__ void fma2(u64&d,u64 a,u64 b){asm("fma.rn.f32x2 %0,%1,%2,%0;":"+l"(d):"l"(a),"l"(b));}
__device__ __forceinline__ void mul2(u64&d,u64 a){asm("mul.rn.f32x2 %0,%0,%1;":"+l"(d):"l"(a));}
__device__ __forceinline__ float2 up2(u64 v){float2 r;asm("mov.b64 {%0,%1},%2;":"=f"(r.x),"=f"(r.y):"l"(v));return r;}

// ---------------------------------------------------------------------------
// Projection: out[m,n] = sum_k X[m,k]W[n,k] + b[n]. 128x64 tile, BK=8,
// 128 threads, 8x8/thread FFMA2, double-buffered smem.
// ---------------------------------------------------------------------------
__global__ void __launch_bounds__(128, 3)
proj_kernel(const float* __restrict__ X, const float* __restrict__ W,
            const float* __restrict__ bias, float* __restrict__ out)
{
    __shared__ __align__(16) float Xs[2][8][132];   // [k][m] transposed
    __shared__ __align__(16) float Ws[2][8][68];    // [k][n] transposed, swizzled
    const int t = threadIdx.x, tk = t & 7, tq = t >> 3;
    const int bm = blockIdx.y * 128, bn = blockIdx.x * 64;
    const int wr = t >> 1, wc = (t & 1) * 4;
    const int pw = wr + ((wr >> 5) & 1) * 4;
    const int kb = tk * 8 + ((tk >> 2) & 1) * 4;

    const float* xp = X + (size_t)(bm + t) * D_;
    const float* wp = W + (size_t)(bn + wr) * D_ + wc;
    float4 xv0 = *(const float4*)xp, xv1 = *(const float4*)(xp + 4);
    float4 wv  = *(const float4*)wp;
    u64 acc[8][4] = {};

    for (int k0 = 0; k0 < D_; k0 += 8) {
        const int bf = (k0 >> 3) & 1;
        Xs[bf][0][t]=xv0.x; Xs[bf][1][t]=xv0.y; Xs[bf][2][t]=xv0.z; Xs[bf][3][t]=xv0.w;
        Xs[bf][4][t]=xv1.x; Xs[bf][5][t]=xv1.y; Xs[bf][6][t]=xv1.z; Xs[bf][7][t]=xv1.w;
        Ws[bf][wc+0][pw]=wv.x; Ws[bf][wc+1][pw]=wv.y;
        Ws[bf][wc+2][pw]=wv.z; Ws[bf][wc+3][pw]=wv.w;
        __syncthreads();
        if (k0 + 8 < D_) {
            xp += 8; wp += 8;
            xv0 = *(const float4*)xp; xv1 = *(const float4*)(xp + 4);
            wv  = *(const float4*)wp;
        }
        #pragma unroll
        for (int kk = 0; kk < 8; kk++) {
            float4 a0 = *(const float4*)&Xs[bf][kk][tq * 8];
            float4 a1 = *(const float4*)&Xs[bf][kk][tq * 8 + 4];
            ulonglong2 b0 = *(const ulonglong2*)&Ws[bf][kk][kb];
            ulonglong2 b1 = *(const ulonglong2*)&Ws[bf][kk][kb + 4];
            float av[8] = {a0.x,a0.y,a0.z,a0.w,a1.x,a1.y,a1.z,a1.w};
            #pragma unroll
            for (int i = 0; i < 8; i++) {
                u64 A = dup2(av[i]);
                fma2(acc[i][0],A,b0.x); fma2(acc[i][1],A,b0.y);
                fma2(acc[i][2],A,b1.x); fma2(acc[i][3],A,b1.y);
            }
        }
        // one sync/iter: reads(i) precede stores(i+2) via sync(i+1) on all threads
    }
    float4 bb0 = *(const float4*)&bias[bn + tk * 8];
    float4 bb1 = *(const float4*)&bias[bn + tk * 8 + 4];
    #pragma unroll
    for (int i = 0; i < 8; i++) {
        size_t base = (size_t)(bm + tq * 8 + i) * D_ + bn + tk * 8;
        float2 e0=up2(acc[i][0]), e1=up2(acc[i][1]), e2=up2(acc[i][2]), e3=up2(acc[i][3]);
        *(float4*)&out[base]   = make_float4(e0.x+bb0.x, e0.y+bb0.y, e1.x+bb0.z, e1.y+bb0.w);
        *(float4*)&out[base+4] = make_float4(e2.x+bb1.x, e2.y+bb1.y, e3.x+bb1.z, e3.y+bb1.w);
    }
}

// ---------------------------------------------------------------------------
// Flash attention: 128 threads, q-tile 128, k-tile 64, 8x8/thread FFMA2.
// ---------------------------------------------------------------------------
__global__ void __launch_bounds__(128, 2)
attn_kernel(const float* __restrict__ Q, const float* __restrict__ K,
            const float* __restrict__ V, const int* __restrict__ mask,
            float* __restrict__ ctx)
{
    extern __shared__ float sm[];
    float (*QsT)[132] = (float(*)[132])sm;                       // [64 d][128 q]
    float (*KsT)[68]  = (float(*)[68])(sm + 64*132);             // [64 d][64 k] swz
    float (*Vs )[68]  = (float(*)[68])(sm + 64*132 + 64*68);     // [64 k][64 d] swz
    float (*PsT)[132] = (float(*)[132])(sm + 64*132 + 2*64*68);  // [64 k][128 q] row-ilv

    const int t = threadIdx.x, tk = t & 7, tq = t >> 3;
    const int b = blockIdx.z, h = blockIdx.y, q0 = blockIdx.x * 128;
    const int kb = tk * 8 + ((tk >> 2) & 1) * 4;
    const int kr = t >> 1, dh = (t & 1) * 32;
    const int pk = kr + ((kr >> 5) & 1) * 4;

    {   // Q transposed, scale folded; thread t owns q-row q0+t
        const float* qg = Q + (size_t)(b * S_ + q0 + t) * D_ + h * 64;
        #pragma unroll
        for (int c = 0; c < 16; c++) {
            float4 v = *(const float4*)(qg + c * 4);
            QsT[4*c+0][t]=v.x*.125f; QsT[4*c+1][t]=v.y*.125f;
            QsT[4*c+2][t]=v.z*.125f; QsT[4*c+3][t]=v.w*.125f;
        }
    }
    u64 o2[8][4] = {};
    float m_i[8], l_i[8];
    #pragma unroll
    for (int i = 0; i < 8; i++) { m_i[i] = -1e30f; l_i[i] = 0.f; }

    for (int k0 = 0; k0 < S_; k0 += 64) {
        // K transposed + V natural (half-row per thread)
        const float* kg = K + (size_t)(b * S_ + k0 + kr) * D_ + h * 64 + dh;
        const float* vg = V + (size_t)(b * S_ + k0 + kr) * D_ + h * 64 + dh;
        #pragma unroll
        for (int c = 0; c < 8; c++) {
            float4 kv = *(const float4*)(kg + c * 4);
            int d = dh + 4 * c;
            KsT[d+0][pk]=kv.x; KsT[d+1][pk]=kv.y; KsT[d+2][pk]=kv.z; KsT[d+3][pk]=kv.w;
            int pc = d + ((d >> 5) & 1) * 4;
            *(float4*)&Vs[kr][pc] = *(const float4*)(vg + c * 4);
        }
        __syncthreads();

        // S = Q K^T
        u64 s2[8][4] = {};
        #pragma unroll 8
        for (int d = 0; d < 64; d++) {
            float4 a0 = *(const float4*)&QsT[d][tq * 8];
            float4 a1 = *(const float4*)&QsT[d][tq * 8 + 4];
            ulonglong2 b0 = *(const ulonglong2*)&KsT[d][kb];
            ulonglong2 b1 = *(const ulonglong2*)&KsT[d][kb + 4];
            float av[8] = {a0.x,a0.y,a0.z,a0.w,a1.x,a1.y,a1.z,a1.w};
            #pragma unroll
            for (int i = 0; i < 8; i++) {
                u64 A = dup2(av[i]);
                fma2(s2[i][0],A,b0.x); fma2(s2[i][1],A,b0.y);
                fma2(s2[i][2],A,b1.x); fma2(s2[i][3],A,b1.y);
            }
        }

        // mask + online softmax, stage P (row-interleaved [j*8+tk])
        const int* mp = mask + (size_t)(q0 + tq * 8) * S_ + k0 + tk * 8;
        #pragma unroll
        for (int i = 0; i < 8; i++) {
            float2 e0=up2(s2[i][0]), e1=up2(s2[i][1]), e2=up2(s2[i][2]), e3=up2(s2[i][3]);
            float p[8] = {e0.x,e0.y,e1.x,e1.y,e2.x,e2.y,e3.x,e3.y};
            int4 m0 = *(const int4*)(mp + (size_t)i * S_);
            int4 m1 = *(const int4*)(mp + (size_t)i * S_ + 4);
            if(m0.x==0)p[0]=-1e9f; if(m0.y==0)p[1]=-1e9f;
            if(m0.z==0)p[2]=-1e9f; if(m0.w==0)p[3]=-1e9f;
            if(m1.x==0)p[4]=-1e9f; if(m1.y==0)p[5]=-1e9f;
            if(m1.z==0)p[6]=-1e9f; if(m1.w==0)p[7]=-1e9f;
            float rm = p[0];
            #pragma unroll
            for (int j = 1; j < 8; j++) rm = fmaxf(rm, p[j]);
            rm = fmaxf(rm, __shfl_xor_sync(0xffffffffu, rm, 1));
            rm = fmaxf(rm, __shfl_xor_sync(0xffffffffu, rm, 2));
            rm = fmaxf(rm, __shfl_xor_sync(0xffffffffu, rm, 4));
            float mn = fmaxf(m_i[i], rm);
            float al = __expf(m_i[i] - mn);
            float rs = 0.f;
            #pragma unroll
            for (int j = 0; j < 8; j++) { p[j] = __expf(p[j] - mn); rs += p[j]; }
            rs += __shfl_xor_sync(0xffffffffu, rs, 1);
            rs += __shfl_xor_sync(0xffffffffu, rs, 2);
            rs += __shfl_xor_sync(0xffffffffu, rs, 4);
            l_i[i] = l_i[i] * al + rs; m_i[i] = mn;
            u64 A = dup2(al);
            mul2(o2[i][0],A); mul2(o2[i][1],A); mul2(o2[i][2],A); mul2(o2[i][3],A);
            #pragma unroll
            for (int j = 0; j < 8; j++) PsT[j * 8 + tk][tq * 8 + i] = p[j];
        }
        __syncthreads();

        // O += P V   (logical kk -> phys row (kk&7)*8 + (kk>>3))
        #pragma unroll 8
        for (int kk = 0; kk < 64; kk++) {
            const float* prow = PsT[(kk & 7) * 8 + (kk >> 3)];
            float4 a0 = *(const float4*)&prow[tq * 8];
            float4 a1 = *(const float4*)&prow[tq * 8 + 4];
            ulonglong2 b0 = *(const ulonglong2*)&Vs[kk][kb];
            ulonglong2 b1 = *(const ulonglong2*)&Vs[kk][kb + 4];
            float av[8] = {a0.x,a0.y,a0.z,a0.w,a1.x,a1.y,a1.z,a1.w};
            #pragma unroll
            for (int i = 0; i < 8; i++) {
                u64 A = dup2(av[i]);
                fma2(o2[i][0],A,b0.x); fma2(o2[i][1],A,b0.y);
                fma2(o2[i][2],A,b1.x); fma2(o2[i][3],A,b1.y);
            }
        }
        __syncthreads();
    }
    #pragma unroll
    for (int i = 0; i < 8; i++) {
        float inv = 1.f / l_i[i];
        float2 e0=up2(o2[i][0]), e1=up2(o2[i][1]), e2=up2(o2[i][2]), e3=up2(o2[i][3]);
        size_t base = (size_t)(b * S_ + q0 + tq * 8 + i) * D_ + h * 64 + tk * 8;
        *(float4*)&ctx[base]   = make_float4(e0.x*inv, e0.y*inv, e1.x*inv, e1.y*inv);
        *(float4*)&ctx[base+4] = make_float4(e2.x*inv, e2.y*inv, e3.x*inv, e3.y*inv);
    }
}

extern "C" void kernel_launch(void* const* d_in, const int* in_sizes, int n_in,
                              void* d_out, int out_size)
{
    const float* q  = (const float*)d_in[0];
    const float* k  = (const float*)d_in[1];
    const float* v  = (const float*)d_in[2];
    const int* mask = (const int*)  d_in[3];
    const float* Wq = (const float*)d_in[4];  const float* bq = (const float*)d_in[5];
    const float* Wk = (const float*)d_in[6];  const float* bk = (const float*)d_in[7];
    const float* Wv = (const float*)d_in[8];  const float* bv = (const float*)d_in[9];
    const float* Wo = (const float*)d_in[10]; const float* bo = (const float*)d_in[11];
    float* out = (float*)d_out;

    float *Qp, *Kp, *Vp, *Cp;
    cudaGetSymbolAddress((void**)&Qp, g_Q);
    cudaGetSymbolAddress((void**)&Kp, g_K);
    cudaGetSymbolAddress((void**)&Vp, g_V);
    cudaGetSymbolAddress((void**)&Cp, g_C);

    dim3 pg(D_ / 64, (B_ * S_) / 128);   // 16 x 32 = 512 CTAs
    proj_kernel<<<pg, 128>>>(q, Wq, bq, Qp);
    proj_kernel<<<pg, 128>>>(k, Wk, bk, Kp);
    proj_kernel<<<pg, 128>>>(v, Wv, bv, Vp);

    const int asmem = (64*132 + 2*64*68 + 64*132) * (int)sizeof(float);  // 102400 B
    cudaFuncSetAttribute(attn_kernel, cudaFuncAttributeMaxDynamicSharedMemorySize, asmem);
    attn_kernel<<<dim3(S_ / 128, H_, B_), 128, asmem>>>(Qp, Kp, Vp, mask, Cp);

    proj_kernel<<<pg, 128>>>(Cp, Wo, bo, out);
}

// round 6
// speedup vs baseline: 1.6320x; 1.3530x over previous
#include <cuda_runtime.h>
#include <cuda_bf16.h>
#include <cstdint>
#define B_ 2
#define S_ 2048
#define D_ 1024
#define H_ 16
typedef unsigned long long u64;

__device__ float g_Q[B_*S_*D_], g_K[B_*S_*D_], g_V[B_*S_*D_], g_C[B_*S_*D_];
__device__ __nv_bfloat16 g_Ah[B_*S_*D_], g_Al[B_*S_*D_];   // activation hi/lo
__device__ __nv_bfloat16 g_Bh[D_*D_],   g_Bl[D_*D_];       // weight hi/lo

__device__ __forceinline__ u64 dup2(float x){u64 r;asm("mov.b64 %0,{%1,%1};":"=l"(r):"f"(x));return r;}
__device__ __forceinline__ void fma2(u64&d,u64 a,u64 b){asm("fma.rn.f32x2 %0,%1,%2,%0;":"+l"(d):"l"(a),"l"(b));}
__device__ __forceinline__ void mul2(u64&d,u64 a){asm("mul.rn.f32x2 %0,%0,%1;":"+l"(d):"l"(a));}
__device__ __forceinline__ float2 up2(u64 v){float2 r;asm("mov.b64 {%0,%1},%2;":"=f"(r.x),"=f"(r.y):"l"(v));return r;}

__device__ __forceinline__ uint32_t smem_u32(const void* p){
    uint32_t a; asm("{ .reg .u64 t; cvta.to.shared.u64 t, %1; cvt.u32.u64 %0, t; }":"=r"(a):"l"(p)); return a;
}
__device__ __forceinline__ void ldsm4(uint32_t* r, uint32_t a){
    asm volatile("ldmatrix.sync.aligned.m8n8.x4.shared.b16 {%0,%1,%2,%3}, [%4];"
        :"=r"(r[0]),"=r"(r[1]),"=r"(r[2]),"=r"(r[3]):"r"(a));
}
__device__ __forceinline__ void mmabf(float* c, const uint32_t* a, uint32_t b0, uint32_t b1){
    asm volatile("mma.sync.aligned.m16n8k16.row.col.f32.bf16.bf16.f32 "
        "{%0,%1,%2,%3}, {%4,%5,%6,%7}, {%8,%9}, {%0,%1,%2,%3};"
        :"+f"(c[0]),"+f"(c[1]),"+f"(c[2]),"+f"(c[3])
        :"r"(a[0]),"r"(a[1]),"r"(a[2]),"r"(a[3]),"r"(b0),"r"(b1));
}
__device__ __forceinline__ void cpa16(uint32_t d, const void* s){
    asm volatile("cp.async.cg.shared.global [%0], [%1], 16;"::"r"(d),"l"(s):"memory");
}

// fp32 -> bf16 hi/lo planes (vectorized by 4)
__global__ void __launch_bounds__(256)
cvt_kernel(const float* __restrict__ in, __nv_bfloat16* __restrict__ hi,
           __nv_bfloat16* __restrict__ lo)
{
    int i = blockIdx.x * 256 + threadIdx.x;
    float4 v = ((const float4*)in)[i];
    float a[4] = {v.x, v.y, v.z, v.w};
    unsigned short h[4], l[4];
    #pragma unroll
    for (int j = 0; j < 4; j++) {
        __nv_bfloat16 hb = __float2bfloat16(a[j]);
        __nv_bfloat16 lb = __float2bfloat16(a[j] - __bfloat162float(hb));
        h[j] = __bfloat16_as_ushort(hb); l[j] = __bfloat16_as_ushort(lb);
    }
    ((uint2*)hi)[i] = make_uint2(h[0]|((uint32_t)h[1]<<16), h[2]|((uint32_t)h[3]<<16));
    ((uint2*)lo)[i] = make_uint2(l[0]|((uint32_t)l[1]<<16), l[2]|((uint32_t)l[3]<<16));
}

// ---------------------------------------------------------------------------
// HMMA bf16x3-split GEMM: out[m,n] = sum_k X[m,k]W[n,k] + b[n].
// 128x128 CTA tile, 8 warps (4Mx2N, warp tile 32x64), BK=32,
// cp.async double-buffered smem, ldmatrix.x4 + mma.sync m16n8k16.
// smem plane: 128 rows x 80B (64B data + 16B pad; ldmatrix conflict-free).
// ---------------------------------------------------------------------------
static constexpr int PLN = 128 * 80;        // 10240 B per plane
static constexpr int STG = 4 * PLN;         // Ah,Al,Bh,Bl
static constexpr int GSM = 2 * STG;         // 81920 B

__global__ void __launch_bounds__(256, 2)
gemm_mma(const __nv_bfloat16* __restrict__ Ah, const __nv_bfloat16* __restrict__ Al,
         const __nv_bfloat16* __restrict__ Bh, const __nv_bfloat16* __restrict__ Bl,
         const float* __restrict__ bias, float* __restrict__ out)
{
    extern __shared__ __align__(128) char sm[];
    const uint32_t sb = smem_u32(sm);
    const int t = threadIdx.x, lane = t & 31, w = t >> 5;
    const int bm = blockIdx.y * 128, bn = blockIdx.x * 128;
    const int mw = (w >> 1) * 32, nw = (w & 1) * 64;

    // cp.async mapping: thread covers row t>>1, 32B at offset (t&1)*32
    const int crow = t >> 1, coff = (t & 1) * 32;
    const char* gAh = (const char*)(Ah + (size_t)(bm + crow) * D_) + coff;
    const char* gAl = (const char*)(Al + (size_t)(bm + crow) * D_) + coff;
    const char* gBh = (const char*)(Bh + (size_t)(bn + crow) * D_) + coff;
    const char* gBl = (const char*)(Bl + (size_t)(bn + crow) * D_) + coff;
    const uint32_t dst0 = sb + crow * 80 + coff;

    float acc[2][8][4] = {};

    // issue chunk c into stage s
    #define ISSUE(c, s) do { \
        uint32_t d = dst0 + (s) * STG; int go = (c) * 64; \
        cpa16(d,           gAh + go); cpa16(d + 16,           gAh + go + 16); \
        cpa16(d + PLN,     gAl + go); cpa16(d + PLN + 16,     gAl + go + 16); \
        cpa16(d + 2*PLN,   gBh + go); cpa16(d + 2*PLN + 16,   gBh + go + 16); \
        cpa16(d + 3*PLN,   gBl + go); cpa16(d + 3*PLN + 16,   gBl + go + 16); \
        asm volatile("cp.async.commit_group;" ::: "memory"); \
    } while (0)

    ISSUE(0, 0);
    const int NCH = D_ / 32;
    for (int c = 0; c < NCH; c++) {
        const int s = c & 1;
        if (c + 1 < NCH) {
            ISSUE(c + 1, s ^ 1);
            asm volatile("cp.async.wait_group 1;" ::: "memory");
        } else {
            asm volatile("cp.async.wait_group 0;" ::: "memory");
        }
        __syncthreads();

        const uint32_t base = sb + s * STG;
        const int arow = mw + (lane & 15);
        const int brow = nw + (lane & 7) + ((lane >> 4) << 3);
        #pragma unroll
        for (int ks = 0; ks < 2; ks++) {
            const int acol = ks * 32 + ((lane >> 4) << 4);
            const int bcol = ks * 32 + (((lane >> 3) & 1) << 4);
            uint32_t ah[2][4], al[2][4];
            #pragma unroll
            for (int mi = 0; mi < 2; mi++) {
                uint32_t ad = base + (arow + mi * 16) * 80 + acol;
                ldsm4(ah[mi], ad);
                ldsm4(al[mi], ad + PLN);
            }
            #pragma unroll
            for (int nf = 0; nf < 4; nf++) {
                uint32_t bd = base + 2 * PLN + (brow + nf * 16) * 80 + bcol;
                uint32_t bh[4], bl[4];
                ldsm4(bh, bd);
                ldsm4(bl, bd + PLN);
                #pragma unroll
                for (int mi = 0; mi < 2; mi++) {
                    mmabf(acc[mi][2*nf],   ah[mi], bh[0], bh[1]);
                    mmabf(acc[mi][2*nf],   ah[mi], bl[0], bl[1]);
                    mmabf(acc[mi][2*nf],   al[mi], bh[0], bh[1]);
                    mmabf(acc[mi][2*nf+1], ah[mi], bh[2], bh[3]);
                    mmabf(acc[mi][2*nf+1], ah[mi], bl[2], bl[3]);
                    mmabf(acc[mi][2*nf+1], al[mi], bh[2], bh[3]);
                }
            }
        }
        __syncthreads();
    }
    #undef ISSUE

    #pragma unroll
    for (int mi = 0; mi < 2; mi++) {
        const int r0 = bm + mw + mi * 16 + (lane >> 2);
        #pragma unroll
        for (int nj = 0; nj < 8; nj++) {
            const int col = bn + nw + nj * 8 + (lane & 3) * 2;
            float2 bv = *(const float2*)&bias[col];
            float* c = acc[mi][nj];
            *(float2*)&out[(size_t)r0 * D_ + col] =
                make_float2(c[0] + bv.x, c[1] + bv.y);
            *(float2*)&out[(size_t)(r0 + 8) * D_ + col] =
                make_float2(c[2] + bv.x, c[3] + bv.y);
        }
    }
}

// ---------------------------------------------------------------------------
// Flash attention (round-4, unchanged): 128 thr, q-tile 128, k-tile 64, FFMA2.
// ---------------------------------------------------------------------------
__global__ void __launch_bounds__(128, 2)
attn_kernel(const float* __restrict__ Q, const float* __restrict__ K,
            const float* __restrict__ V, const int* __restrict__ mask,
            float* __restrict__ ctx)
{
    extern __shared__ float smf[];
    float (*QsT)[132] = (float(*)[132])smf;
    float (*KsT)[68]  = (float(*)[68])(smf + 64*132);
    float (*Vs )[68]  = (float(*)[68])(smf + 64*132 + 64*68);
    float (*PsT)[132] = (float(*)[132])(smf + 64*132 + 2*64*68);

    const int t = threadIdx.x, tk = t & 7, tq = t >> 3;
    const int b = blockIdx.z, h = blockIdx.y, q0 = blockIdx.x * 128;
    const int kb = tk * 8 + ((tk >> 2) & 1) * 4;
    const int kr = t >> 1, dh = (t & 1) * 32;
    const int pk = kr + ((kr >> 5) & 1) * 4;

    {
        const float* qg = Q + (size_t)(b * S_ + q0 + t) * D_ + h * 64;
        #pragma unroll
        for (int c = 0; c < 16; c++) {
            float4 v = *(const float4*)(qg + c * 4);
            QsT[4*c+0][t]=v.x*.125f; QsT[4*c+1][t]=v.y*.125f;
            QsT[4*c+2][t]=v.z*.125f; QsT[4*c+3][t]=v.w*.125f;
        }
    }
    u64 o2[8][4] = {};
    float m_i[8], l_i[8];
    #pragma unroll
    for (int i = 0; i < 8; i++) { m_i[i] = -1e30f; l_i[i] = 0.f; }

    for (int k0 = 0; k0 < S_; k0 += 64) {
        const float* kg = K + (size_t)(b * S_ + k0 + kr) * D_ + h * 64 + dh;
        const float* vg = V + (size_t)(b * S_ + k0 + kr) * D_ + h * 64 + dh;
        #pragma unroll
        for (int c = 0; c < 8; c++) {
            float4 kv = *(const float4*)(kg + c * 4);
            int d = dh + 4 * c;
            KsT[d+0][pk]=kv.x; KsT[d+1][pk]=kv.y; KsT[d+2][pk]=kv.z; KsT[d+3][pk]=kv.w;
            int pc = d + ((d >> 5) & 1) * 4;
            *(float4*)&Vs[kr][pc] = *(const float4*)(vg + c * 4);
        }
        __syncthreads();

        u64 s2[8][4] = {};
        #pragma unroll 8
        for (int d = 0; d < 64; d++) {
            float4 a0 = *(const float4*)&QsT[d][tq * 8];
            float4 a1 = *(const float4*)&QsT[d][tq * 8 + 4];
            ulonglong2 b0 = *(const ulonglong2*)&KsT[d][kb];
            ulonglong2 b1 = *(const ulonglong2*)&KsT[d][kb + 4];
            float av[8] = {a0.x,a0.y,a0.z,a0.w,a1.x,a1.y,a1.z,a1.w};
            #pragma unroll
            for (int i = 0; i < 8; i++) {
                u64 A = dup2(av[i]);
                fma2(s2[i][0],A,b0.x); fma2(s2[i][1],A,b0.y);
                fma2(s2[i][2],A,b1.x); fma2(s2[i][3],A,b1.y);
            }
        }

        const int* mp = mask + (size_t)(q0 + tq * 8) * S_ + k0 + tk * 8;
        #pragma unroll
        for (int i = 0; i < 8; i++) {
            float2 e0=up2(s2[i][0]), e1=up2(s2[i][1]), e2=up2(s2[i][2]), e3=up2(s2[i][3]);
            float p[8] = {e0.x,e0.y,e1.x,e1.y,e2.x,e2.y,e3.x,e3.y};
            int4 m0 = *(const int4*)(mp + (size_t)i * S_);
            int4 m1 = *(const int4*)(mp + (size_t)i * S_ + 4);
            if(m0.x==0)p[0]=-1e9f; if(m0.y==0)p[1]=-1e9f;
            if(m0.z==0)p[2]=-1e9f; if(m0.w==0)p[3]=-1e9f;
            if(m1.x==0)p[4]=-1e9f; if(m1.y==0)p[5]=-1e9f;
            if(m1.z==0)p[6]=-1e9f; if(m1.w==0)p[7]=-1e9f;
            float rm = p[0];
            #pragma unroll
            for (int j = 1; j < 8; j++) rm = fmaxf(rm, p[j]);
            rm = fmaxf(rm, __shfl_xor_sync(0xffffffffu, rm, 1));
            rm = fmaxf(rm, __shfl_xor_sync(0xffffffffu, rm, 2));
            rm = fmaxf(rm, __shfl_xor_sync(0xffffffffu, rm, 4));
            float mn = fmaxf(m_i[i], rm);
            float al = __expf(m_i[i] - mn);
            float rs = 0.f;
            #pragma unroll
            for (int j = 0; j < 8; j++) { p[j] = __expf(p[j] - mn); rs += p[j]; }
            rs += __shfl_xor_sync(0xffffffffu, rs, 1);
            rs += __shfl_xor_sync(0xffffffffu, rs, 2);
            rs += __shfl_xor_sync(0xffffffffu, rs, 4);
            l_i[i] = l_i[i] * al + rs; m_i[i] = mn;
            u64 A = dup2(al);
            mul2(o2[i][0],A); mul2(o2[i][1],A); mul2(o2[i][2],A); mul2(o2[i][3],A);
            #pragma unroll
            for (int j = 0; j < 8; j++) PsT[j * 8 + tk][tq * 8 + i] = p[j];
        }
        __syncthreads();

        #pragma unroll 8
        for (int kk = 0; kk < 64; kk++) {
            const float* prow = PsT[(kk & 7) * 8 + (kk >> 3)];
            float4 a0 = *(const float4*)&prow[tq * 8];
            float4 a1 = *(const float4*)&prow[tq * 8 + 4];
            ulonglong2 b0 = *(const ulonglong2*)&Vs[kk][kb];
            ulonglong2 b1 = *(const ulonglong2*)&Vs[kk][kb + 4];
            float av[8] = {a0.x,a0.y,a0.z,a0.w,a1.x,a1.y,a1.z,a1.w};
            #pragma unroll
            for (int i = 0; i < 8; i++) {
                u64 A = dup2(av[i]);
                fma2(o2[i][0],A,b0.x); fma2(o2[i][1],A,b0.y);
                fma2(o2[i][2],A,b1.x); fma2(o2[i][3],A,b1.y);
            }
        }
        __syncthreads();
    }
    #pragma unroll
    for (int i = 0; i < 8; i++) {
        float inv = 1.f / l_i[i];
        float2 e0=up2(o2[i][0]), e1=up2(o2[i][1]), e2=up2(o2[i][2]), e3=up2(o2[i][3]);
        size_t base = (size_t)(b * S_ + q0 + tq * 8 + i) * D_ + h * 64 + tk * 8;
        *(float4*)&ctx[base]   = make_float4(e0.x*inv, e0.y*inv, e1.x*inv, e1.y*inv);
        *(float4*)&ctx[base+4] = make_float4(e2.x*inv, e2.y*inv, e3.x*inv, e3.y*inv);
    }
}

extern "C" void kernel_launch(void* const* d_in, const int* in_sizes, int n_in,
                              void* d_out, int out_size)
{
    const float* q  = (const float*)d_in[0];
    const float* k  = (const float*)d_in[1];
    const float* v  = (const float*)d_in[2];
    const int* mask = (const int*)  d_in[3];
    const float* Wq = (const float*)d_in[4];  const float* bq = (const float*)d_in[5];
    const float* Wk = (const float*)d_in[6];  const float* bk = (const float*)d_in[7];
    const float* Wv = (const float*)d_in[8];  const float* bv = (const float*)d_in[9];
    const float* Wo = (const float*)d_in[10]; const float* bo = (const float*)d_in[11];
    float* out = (float*)d_out;

    float *Qp, *Kp, *Vp, *Cp;
    __nv_bfloat16 *Ahp, *Alp, *Bhp, *Blp;
    cudaGetSymbolAddress((void**)&Qp, g_Q);
    cudaGetSymbolAddress((void**)&Kp, g_K);
    cudaGetSymbolAddress((void**)&Vp, g_V);
    cudaGetSymbolAddress((void**)&Cp, g_C);
    cudaGetSymbolAddress((void**)&Ahp, g_Ah);
    cudaGetSymbolAddress((void**)&Alp, g_Al);
    cudaGetSymbolAddress((void**)&Bhp, g_Bh);
    cudaGetSymbolAddress((void**)&Blp, g_Bl);

    const int MA4 = (B_ * S_ * D_) / 4 / 256;   // act cvt grid
    const int MW4 = (D_ * D_) / 4 / 256;        // weight cvt grid
    dim3 gg(D_ / 128, (B_ * S_) / 128);         // 8 x 32

    cudaFuncSetAttribute(gemm_mma, cudaFuncAttributeMaxDynamicSharedMemorySize, GSM);

    cvt_kernel<<<MA4, 256>>>(q, Ahp, Alp);
    cvt_kernel<<<MW4, 256>>>(Wq, Bhp, Blp);
    gemm_mma<<<gg, 256, GSM>>>(Ahp, Alp, Bhp, Blp, bq, Qp);

    cvt_kernel<<<MA4, 256>>>(k, Ahp, Alp);
    cvt_kernel<<<MW4, 256>>>(Wk, Bhp, Blp);
    gemm_mma<<<gg, 256, GSM>>>(Ahp, Alp, Bhp, Blp, bk, Kp);

    cvt_kernel<<<MA4, 256>>>(v, Ahp, Alp);
    cvt_kernel<<<MW4, 256>>>(Wv, Bhp, Blp);
    gemm_mma<<<gg, 256, GSM>>>(Ahp, Alp, Bhp, Blp, bv, Vp);

    const int asmem = (64*132 + 2*64*68 + 64*132) * (int)sizeof(float);  // 102400 B
    cudaFuncSetAttribute(attn_kernel, cudaFuncAttributeMaxDynamicSharedMemorySize, asmem);
    attn_kernel<<<dim3(S_ / 128, H_, B_), 128, asmem>>>(Qp, Kp, Vp, mask, Cp);

    cvt_kernel<<<MA4, 256>>>(Cp, Ahp, Alp);
    cvt_kernel<<<MW4, 256>>>(Wo, Bhp, Blp);
    gemm_mma<<<gg, 256, GSM>>>(Ahp, Alp, Bhp, Blp, bo, out);
}

// round 7
// speedup vs baseline: 2.7371x; 1.6772x over previous
#include <cuda_runtime.h>
#include <cuda_bf16.h>
#include <cstdint>
#define B_ 2
#define S_ 2048
#define D_ 1024
#define H_ 16

__device__ float g_Q[B_*S_*D_], g_K[B_*S_*D_], g_V[B_*S_*D_], g_C[B_*S_*D_];
__device__ __nv_bfloat16 g_Ah[B_*S_*D_], g_Al[B_*S_*D_];     // gemm act hi/lo
__device__ __nv_bfloat16 g_Bh[D_*D_],   g_Bl[D_*D_];         // gemm wgt hi/lo
__device__ __nv_bfloat16 g_Qh[B_*S_*D_], g_Ql[B_*S_*D_];     // attn Q planes
__device__ __nv_bfloat16 g_Kh[B_*S_*D_], g_Kl[B_*S_*D_];     // attn K planes
__device__ __nv_bfloat16 g_Vth[B_*S_*D_], g_Vtl[B_*S_*D_];   // attn V^T planes [b][h][d][s]

__device__ __forceinline__ uint32_t smem_u32(const void* p){
    uint32_t a; asm("{ .reg .u64 t; cvta.to.shared.u64 t, %1; cvt.u32.u64 %0, t; }":"=r"(a):"l"(p)); return a;
}
__device__ __forceinline__ void ldsm4(uint32_t* r, uint32_t a){
    asm volatile("ldmatrix.sync.aligned.m8n8.x4.shared.b16 {%0,%1,%2,%3}, [%4];"
        :"=r"(r[0]),"=r"(r[1]),"=r"(r[2]),"=r"(r[3]):"r"(a));
}
__device__ __forceinline__ void mmabf(float* c, const uint32_t* a, uint32_t b0, uint32_t b1){
    asm volatile("mma.sync.aligned.m16n8k16.row.col.f32.bf16.bf16.f32 "
        "{%0,%1,%2,%3}, {%4,%5,%6,%7}, {%8,%9}, {%0,%1,%2,%3};"
        :"+f"(c[0]),"+f"(c[1]),"+f"(c[2]),"+f"(c[3])
        :"r"(a[0]),"r"(a[1]),"r"(a[2]),"r"(a[3]),"r"(b0),"r"(b1));
}
__device__ __forceinline__ void cpa16(uint32_t d, const void* s){
    asm volatile("cp.async.cg.shared.global [%0], [%1], 16;"::"r"(d),"l"(s):"memory");
}
__device__ __forceinline__ uint32_t pk2(float a, float b){
    __nv_bfloat162 h = __floats2bfloat162_rn(a, b);
    return *reinterpret_cast<uint32_t*>(&h);
}
__device__ __forceinline__ float bflo(float v){           // residual after bf16 round
    return v - __bfloat162float(__float2bfloat16(v));
}

// ---------------- fp32 -> bf16 hi/lo planes ----------------
__global__ void __launch_bounds__(256)
cvt_kernel(const float* __restrict__ in, __nv_bfloat16* __restrict__ hi,
           __nv_bfloat16* __restrict__ lo)
{
    int i = blockIdx.x * 256 + threadIdx.x;
    float4 v = ((const float4*)in)[i];
    float a[4] = {v.x, v.y, v.z, v.w};
    unsigned short h[4], l[4];
    #pragma unroll
    for (int j = 0; j < 4; j++) {
        __nv_bfloat16 hb = __float2bfloat16(a[j]);
        h[j] = __bfloat16_as_ushort(hb);
        l[j] = __bfloat16_as_ushort(__float2bfloat16(a[j] - __bfloat162float(hb)));
    }
    ((uint2*)hi)[i] = make_uint2(h[0]|((uint32_t)h[1]<<16), h[2]|((uint32_t)h[3]<<16));
    ((uint2*)lo)[i] = make_uint2(l[0]|((uint32_t)l[1]<<16), l[2]|((uint32_t)l[3]<<16));
}
// same, with attention scale folded in
__global__ void __launch_bounds__(256)
cvt_scale_kernel(const float* __restrict__ in, __nv_bfloat16* __restrict__ hi,
                 __nv_bfloat16* __restrict__ lo)
{
    int i = blockIdx.x * 256 + threadIdx.x;
    float4 v = ((const float4*)in)[i];
    float a[4] = {v.x*.125f, v.y*.125f, v.z*.125f, v.w*.125f};
    unsigned short h[4], l[4];
    #pragma unroll
    for (int j = 0; j < 4; j++) {
        __nv_bfloat16 hb = __float2bfloat16(a[j]);
        h[j] = __bfloat16_as_ushort(hb);
        l[j] = __bfloat16_as_ushort(__float2bfloat16(a[j] - __bfloat162float(hb)));
    }
    ((uint2*)hi)[i] = make_uint2(h[0]|((uint32_t)h[1]<<16), h[2]|((uint32_t)h[3]<<16));
    ((uint2*)lo)[i] = make_uint2(l[0]|((uint32_t)l[1]<<16), l[2]|((uint32_t)l[3]<<16));
}
// V[b][s][h*64+d] -> Vt[b][h][d][s] hi/lo (32x32 smem transpose)
__global__ void __launch_bounds__(256)
cvtT_kernel(const float* __restrict__ V, __nv_bfloat16* __restrict__ oh,
            __nv_bfloat16* __restrict__ ol)
{
    __shared__ float tile[32][33];
    const int s0 = blockIdx.x*32, d0 = blockIdx.y*32, b = blockIdx.z;
    const int tx = threadIdx.x & 31, ty = threadIdx.x >> 5;
    #pragma unroll
    for (int i = 0; i < 4; i++)
        tile[ty+8*i][tx] = V[((size_t)(b*S_+s0+ty+8*i))*D_ + d0+tx];
    __syncthreads();
    const int hh = d0 >> 6, dl = d0 & 63;
    #pragma unroll
    for (int i = 0; i < 4; i++) {
        int dr = ty + 8*i;
        float v = tile[tx][dr];
        __nv_bfloat16 hb = __float2bfloat16(v);
        size_t a = ((size_t)((b*H_+hh)*64 + dl + dr))*S_ + s0 + tx;
        oh[a] = hb; ol[a] = __float2bfloat16(v - __bfloat162float(hb));
    }
}

// ---------------------------------------------------------------------------
// HMMA bf16x3-split GEMM (round-6, verified): out = X W^T + b, 128x128 tile.
// ---------------------------------------------------------------------------
static constexpr int PLN = 128 * 80;
static constexpr int STG = 4 * PLN;
static constexpr int GSM = 2 * STG;

__global__ void __launch_bounds__(256, 2)
gemm_mma(const __nv_bfloat16* __restrict__ Ah, const __nv_bfloat16* __restrict__ Al,
         const __nv_bfloat16* __restrict__ Bh, const __nv_bfloat16* __restrict__ Bl,
         const float* __restrict__ bias, float* __restrict__ out)
{
    extern __shared__ __align__(128) char sm[];
    const uint32_t sb = smem_u32(sm);
    const int t = threadIdx.x, lane = t & 31, w = t >> 5;
    const int bm = blockIdx.y * 128, bn = blockIdx.x * 128;
    const int mw = (w >> 1) * 32, nw = (w & 1) * 64;
    const int crow = t >> 1, coff = (t & 1) * 32;
    const char* gAh = (const char*)(Ah + (size_t)(bm + crow) * D_) + coff;
    const char* gAl = (const char*)(Al + (size_t)(bm + crow) * D_) + coff;
    const char* gBh = (const char*)(Bh + (size_t)(bn + crow) * D_) + coff;
    const char* gBl = (const char*)(Bl + (size_t)(bn + crow) * D_) + coff;
    const uint32_t dst0 = sb + crow * 80 + coff;

    float acc[2][8][4] = {};
    #define ISSUE(c, s) do { \
        uint32_t d = dst0 + (s) * STG; int go = (c) * 64; \
        cpa16(d,           gAh + go); cpa16(d + 16,           gAh + go + 16); \
        cpa16(d + PLN,     gAl + go); cpa16(d + PLN + 16,     gAl + go + 16); \
        cpa16(d + 2*PLN,   gBh + go); cpa16(d + 2*PLN + 16,   gBh + go + 16); \
        cpa16(d + 3*PLN,   gBl + go); cpa16(d + 3*PLN + 16,   gBl + go + 16); \
        asm volatile("cp.async.commit_group;" ::: "memory"); \
    } while (0)

    ISSUE(0, 0);
    const int NCH = D_ / 32;
    for (int c = 0; c < NCH; c++) {
        const int s = c & 1;
        if (c + 1 < NCH) { ISSUE(c + 1, s ^ 1); asm volatile("cp.async.wait_group 1;" ::: "memory"); }
        else             { asm volatile("cp.async.wait_group 0;" ::: "memory"); }
        __syncthreads();
        const uint32_t base = sb + s * STG;
        const int arow = mw + (lane & 15);
        const int brow = nw + (lane & 7) + ((lane >> 4) << 3);
        #pragma unroll
        for (int ks = 0; ks < 2; ks++) {
            const int acol = ks * 32 + ((lane >> 4) << 4);
            const int bcol = ks * 32 + (((lane >> 3) & 1) << 4);
            uint32_t ah[2][4], al[2][4];
            #pragma unroll
            for (int mi = 0; mi < 2; mi++) {
                uint32_t ad = base + (arow + mi * 16) * 80 + acol;
                ldsm4(ah[mi], ad); ldsm4(al[mi], ad + PLN);
            }
            #pragma unroll
            for (int nf = 0; nf < 4; nf++) {
                uint32_t bd = base + 2 * PLN + (brow + nf * 16) * 80 + bcol;
                uint32_t bh[4], bl[4];
                ldsm4(bh, bd); ldsm4(bl, bd + PLN);
                #pragma unroll
                for (int mi = 0; mi < 2; mi++) {
                    mmabf(acc[mi][2*nf],   ah[mi], bh[0], bh[1]);
                    mmabf(acc[mi][2*nf],   ah[mi], bl[0], bl[1]);
                    mmabf(acc[mi][2*nf],   al[mi], bh[0], bh[1]);
                    mmabf(acc[mi][2*nf+1], ah[mi], bh[2], bh[3]);
                    mmabf(acc[mi][2*nf+1], ah[mi], bl[2], bl[3]);
                    mmabf(acc[mi][2*nf+1], al[mi], bh[2], bh[3]);
                }
            }
        }
        __syncthreads();
    }
    #undef ISSUE
    #pragma unroll
    for (int mi = 0; mi < 2; mi++) {
        const int r0 = bm + mw + mi * 16 + (lane >> 2);
        #pragma unroll
        for (int nj = 0; nj < 8; nj++) {
            const int col = bn + nw + nj * 8 + (lane & 3) * 2;
            float2 bv = *(const float2*)&bias[col];
            float* c = acc[mi][nj];
            *(float2*)&out[(size_t)r0 * D_ + col] = make_float2(c[0] + bv.x, c[1] + bv.y);
            *(float2*)&out[(size_t)(r0 + 8) * D_ + col] = make_float2(c[2] + bv.x, c[3] + bv.y);
        }
    }
}

// ---------------------------------------------------------------------------
// HMMA flash attention: CTA = (128 q) x head. 4 warps, warp = 32 q rows.
// S = Qh/l x Kh/l (3 terms), softmax on C-frags in regs, P repacked as
// A-frags (hi/lo) directly, O += P x Vt (3 terms). All tiles bf16 via
// cp.async, ldmatrix stride 144B (conflict-free).
// ---------------------------------------------------------------------------
static constexpr int KST  = 144;          // bytes per smem row (128 data + 16 pad)
static constexpr int KPL  = 64 * KST;     // 9216 per plane
static constexpr int ASTG = 4 * KPL;      // Kh,Kl,Vth,Vtl = 36864
static constexpr int ASM  = 2 * ASTG;     // 73728
static constexpr int QLO  = 128 * KST;    // Q lo-plane offset in staging

__global__ void __launch_bounds__(128, 2)
attn_mma(const __nv_bfloat16* __restrict__ Qh, const __nv_bfloat16* __restrict__ Ql,
         const __nv_bfloat16* __restrict__ Kh, const __nv_bfloat16* __restrict__ Kl,
         const __nv_bfloat16* __restrict__ Vth, const __nv_bfloat16* __restrict__ Vtl,
         const int* __restrict__ mask, float* __restrict__ ctx)
{
    extern __shared__ __align__(128) char sm[];
    const uint32_t sb = smem_u32(sm);
    const int t = threadIdx.x, lane = t & 31, w = t >> 5;
    const int b = blockIdx.z, h = blockIdx.y, q0 = blockIdx.x * 128;
    const int g = lane >> 2, qt = lane & 3;

    // ---- prologue: stage Q tile (hi/lo) and extract persistent A-frags ----
    {
        const char* ph = (const char*)(Qh + ((size_t)(b*S_ + q0 + t))*D_ + h*64);
        const char* pl = (const char*)(Ql + ((size_t)(b*S_ + q0 + t))*D_ + h*64);
        uint32_t d = sb + t * KST;
        #pragma unroll
        for (int i = 0; i < 8; i++) { cpa16(d + i*16, ph + i*16); cpa16(d + QLO + i*16, pl + i*16); }
        asm volatile("cp.async.commit_group;" ::: "memory");
        asm volatile("cp.async.wait_group 0;" ::: "memory");
    }
    __syncthreads();
    uint32_t qfh[2][4][4], qfl[2][4][4];
    #pragma unroll
    for (int mi = 0; mi < 2; mi++)
        #pragma unroll
        for (int kc = 0; kc < 4; kc++) {
            uint32_t a = sb + (w*32 + mi*16 + (lane & 15)) * KST + kc*32 + ((lane >> 4) << 4);
            ldsm4(qfh[mi][kc], a);
            ldsm4(qfl[mi][kc], a + QLO);
        }
    __syncthreads();   // staging region about to be overwritten by K/V stage 0

    float o[2][8][4] = {};
    float m_i[2][2], l_i[2][2];
    #pragma unroll
    for (int mi = 0; mi < 2; mi++) { m_i[mi][0]=m_i[mi][1]=-1e30f; l_i[mi][0]=l_i[mi][1]=0.f; }

    // K/V tile issue: thread covers row t>>1, 64B half (t&1)
    const int krow = t >> 1, khalf = (t & 1) * 64;
    #define AISSUE(c, s) do { \
        uint32_t dd = sb + (s)*ASTG + krow*KST + khalf; \
        const char* pkh = (const char*)(Kh  + ((size_t)(b*S_ + (c)*64 + krow))*D_ + h*64) + khalf; \
        const char* pkl = (const char*)(Kl  + ((size_t)(b*S_ + (c)*64 + krow))*D_ + h*64) + khalf; \
        const char* pvh = (const char*)(Vth + ((size_t)((b*H_+h)*64 + krow))*S_ + (c)*64) + khalf; \
        const char* pvl = (const char*)(Vtl + ((size_t)((b*H_+h)*64 + krow))*S_ + (c)*64) + khalf; \
        _Pragma("unroll") for (int i = 0; i < 4; i++) { \
            cpa16(dd + i*16,         pkh + i*16); cpa16(dd + KPL + i*16,   pkl + i*16); \
            cpa16(dd + 2*KPL + i*16, pvh + i*16); cpa16(dd + 3*KPL + i*16, pvl + i*16); } \
        asm volatile("cp.async.commit_group;" ::: "memory"); \
    } while (0)

    AISSUE(0, 0);
    const int NT = S_ / 64;
    for (int c = 0; c < NT; c++) {
        const int s = c & 1;
        if (c + 1 < NT) { AISSUE(c + 1, s ^ 1); asm volatile("cp.async.wait_group 1;" ::: "memory"); }
        else            { asm volatile("cp.async.wait_group 0;" ::: "memory"); }
        __syncthreads();
        const uint32_t base = sb + s * ASTG;
        const int brow = (lane & 7) + ((lane >> 4) << 3);
        const int bcsel = ((lane >> 3) & 1) << 4;

        // ---- S = Q K^T (3 split terms) ----
        float sacc[2][8][4] = {};
        #pragma unroll
        for (int kc = 0; kc < 4; kc++)
            #pragma unroll
            for (int np = 0; np < 4; np++) {
                uint32_t ad = base + (np*16 + brow) * KST + kc*32 + bcsel;
                uint32_t bh[4], bl[4];
                ldsm4(bh, ad); ldsm4(bl, ad + KPL);
                #pragma unroll
                for (int mi = 0; mi < 2; mi++) {
                    mmabf(sacc[mi][2*np],   qfh[mi][kc], bh[0], bh[1]);
                    mmabf(sacc[mi][2*np],   qfh[mi][kc], bl[0], bl[1]);
                    mmabf(sacc[mi][2*np],   qfl[mi][kc], bh[0], bh[1]);
                    mmabf(sacc[mi][2*np+1], qfh[mi][kc], bh[2], bh[3]);
                    mmabf(sacc[mi][2*np+1], qfh[mi][kc], bl[2], bl[3]);
                    mmabf(sacc[mi][2*np+1], qfl[mi][kc], bh[2], bh[3]);
                }
            }

        // ---- mask + online softmax on fragments ----
        #pragma unroll
        for (int mi = 0; mi < 2; mi++) {
            const int r0 = q0 + w*32 + mi*16 + g;
            const int cb = c*64 + qt*2;
            float mx0 = -1e30f, mx1 = -1e30f;
            #pragma unroll
            for (int nf = 0; nf < 8; nf++) {
                int2 mk0 = *(const int2*)&mask[(size_t)r0*S_ + cb + nf*8];
                int2 mk1 = *(const int2*)&mask[(size_t)(r0+8)*S_ + cb + nf*8];
                if (mk0.x == 0) sacc[mi][nf][0] = -1e9f;
                if (mk0.y == 0) sacc[mi][nf][1] = -1e9f;
                if (mk1.x == 0) sacc[mi][nf][2] = -1e9f;
                if (mk1.y == 0) sacc[mi][nf][3] = -1e9f;
                mx0 = fmaxf(mx0, fmaxf(sacc[mi][nf][0], sacc[mi][nf][1]));
                mx1 = fmaxf(mx1, fmaxf(sacc[mi][nf][2], sacc[mi][nf][3]));
            }
            mx0 = fmaxf(mx0, __shfl_xor_sync(0xffffffffu, mx0, 1));
            mx0 = fmaxf(mx0, __shfl_xor_sync(0xffffffffu, mx0, 2));
            mx1 = fmaxf(mx1, __shfl_xor_sync(0xffffffffu, mx1, 1));
            mx1 = fmaxf(mx1, __shfl_xor_sync(0xffffffffu, mx1, 2));
            float mn0 = fmaxf(m_i[mi][0], mx0), mn1 = fmaxf(m_i[mi][1], mx1);
            float al0 = __expf(m_i[mi][0] - mn0), al1 = __expf(m_i[mi][1] - mn1);
            float s0 = 0.f, s1 = 0.f;
            #pragma unroll
            for (int nf = 0; nf < 8; nf++) {
                sacc[mi][nf][0] = __expf(sacc[mi][nf][0] - mn0);
                sacc[mi][nf][1] = __expf(sacc[mi][nf][1] - mn0);
                sacc[mi][nf][2] = __expf(sacc[mi][nf][2] - mn1);
                sacc[mi][nf][3] = __expf(sacc[mi][nf][3] - mn1);
                s0 += sacc[mi][nf][0] + sacc[mi][nf][1];
                s1 += sacc[mi][nf][2] + sacc[mi][nf][3];
            }
            s0 += __shfl_xor_sync(0xffffffffu, s0, 1);
            s0 += __shfl_xor_sync(0xffffffffu, s0, 2);
            s1 += __shfl_xor_sync(0xffffffffu, s1, 1);
            s1 += __shfl_xor_sync(0xffffffffu, s1, 2);
            l_i[mi][0] = l_i[mi][0]*al0 + s0; m_i[mi][0] = mn0;
            l_i[mi][1] = l_i[mi][1]*al1 + s1; m_i[mi][1] = mn1;
            #pragma unroll
            for (int nf = 0; nf < 8; nf++) {
                o[mi][nf][0] *= al0; o[mi][nf][1] *= al0;
                o[mi][nf][2] *= al1; o[mi][nf][3] *= al1;
            }
        }

        // ---- O += P V (P from sacc, hi/lo repack; 3 split terms) ----
        #pragma unroll
        for (int kc = 0; kc < 4; kc++) {
            uint32_t ph[2][4], pl[2][4];
            #pragma unroll
            for (int mi = 0; mi < 2; mi++) {
                float* c0 = sacc[mi][2*kc];
                float* c1 = sacc[mi][2*kc+1];
                ph[mi][0] = pk2(c0[0], c0[1]); pl[mi][0] = pk2(bflo(c0[0]), bflo(c0[1]));
                ph[mi][1] = pk2(c0[2], c0[3]); pl[mi][1] = pk2(bflo(c0[2]), bflo(c0[3]));
                ph[mi][2] = pk2(c1[0], c1[1]); pl[mi][2] = pk2(bflo(c1[0]), bflo(c1[1]));
                ph[mi][3] = pk2(c1[2], c1[3]); pl[mi][3] = pk2(bflo(c1[2]), bflo(c1[3]));
            }
            #pragma unroll
            for (int np = 0; np < 4; np++) {
                uint32_t vd = base + 2*KPL + (np*16 + brow) * KST + kc*32 + bcsel;
                uint32_t vh[4], vl[4];
                ldsm4(vh, vd); ldsm4(vl, vd + KPL);
                #pragma unroll
                for (int mi = 0; mi < 2; mi++) {
                    mmabf(o[mi][2*np],   ph[mi], vh[0], vh[1]);
                    mmabf(o[mi][2*np],   ph[mi], vl[0], vl[1]);
                    mmabf(o[mi][2*np],   pl[mi], vh[0], vh[1]);
                    mmabf(o[mi][2*np+1], ph[mi], vh[2], vh[3]);
                    mmabf(o[mi][2*np+1], ph[mi], vl[2], vl[3]);
                    mmabf(o[mi][2*np+1], pl[mi], vh[2], vh[3]);
                }
            }
        }
        __syncthreads();
    }
    #undef AISSUE

    #pragma unroll
    for (int mi = 0; mi < 2; mi++) {
        const int r0 = q0 + w*32 + mi*16 + g;
        const float i0 = 1.f / l_i[mi][0], i1 = 1.f / l_i[mi][1];
        #pragma unroll
        for (int nf = 0; nf < 8; nf++) {
            const int col = h*64 + nf*8 + qt*2;
            *(float2*)&ctx[(size_t)(b*S_ + r0)*D_ + col] =
                make_float2(o[mi][nf][0]*i0, o[mi][nf][1]*i0);
            *(float2*)&ctx[(size_t)(b*S_ + r0 + 8)*D_ + col] =
                make_float2(o[mi][nf][2]*i1, o[mi][nf][3]*i1);
        }
    }
}

// ---------------------------------------------------------------------------
extern "C" void kernel_launch(void* const* d_in, const int* in_sizes, int n_in,
                              void* d_out, int out_size)
{
    const float* q  = (const float*)d_in[0];
    const float* k  = (const float*)d_in[1];
    const float* v  = (const float*)d_in[2];
    const int* mask = (const int*)  d_in[3];
    const float* Wq = (const float*)d_in[4];  const float* bq = (const float*)d_in[5];
    const float* Wk = (const float*)d_in[6];  const float* bk = (const float*)d_in[7];
    const float* Wv = (const float*)d_in[8];  const float* bv = (const float*)d_in[9];
    const float* Wo = (const float*)d_in[10]; const float* bo = (const float*)d_in[11];
    float* out = (float*)d_out;

    float *Qp, *Kp, *Vp, *Cp;
    __nv_bfloat16 *Ahp, *Alp, *Bhp, *Blp, *Qhp, *Qlp, *Khp, *Klp, *Vhp, *Vlp;
    cudaGetSymbolAddress((void**)&Qp, g_Q);   cudaGetSymbolAddress((void**)&Kp, g_K);
    cudaGetSymbolAddress((void**)&Vp, g_V);   cudaGetSymbolAddress((void**)&Cp, g_C);
    cudaGetSymbolAddress((void**)&Ahp, g_Ah); cudaGetSymbolAddress((void**)&Alp, g_Al);
    cudaGetSymbolAddress((void**)&Bhp, g_Bh); cudaGetSymbolAddress((void**)&Blp, g_Bl);
    cudaGetSymbolAddress((void**)&Qhp, g_Qh); cudaGetSymbolAddress((void**)&Qlp, g_Ql);
    cudaGetSymbolAddress((void**)&Khp, g_Kh); cudaGetSymbolAddress((void**)&Klp, g_Kl);
    cudaGetSymbolAddress((void**)&Vhp, g_Vth); cudaGetSymbolAddress((void**)&Vlp, g_Vtl);

    const int MA4 = (B_ * S_ * D_) / 4 / 256;
    const int MW4 = (D_ * D_) / 4 / 256;
    dim3 gg(D_ / 128, (B_ * S_) / 128);

    cudaFuncSetAttribute(gemm_mma, cudaFuncAttributeMaxDynamicSharedMemorySize, GSM);
    cudaFuncSetAttribute(attn_mma, cudaFuncAttributeMaxDynamicSharedMemorySize, ASM);

    cvt_kernel<<<MA4, 256>>>(q, Ahp, Alp);
    cvt_kernel<<<MW4, 256>>>(Wq, Bhp, Blp);
    gemm_mma<<<gg, 256, GSM>>>(Ahp, Alp, Bhp, Blp, bq, Qp);

    cvt_kernel<<<MA4, 256>>>(k, Ahp, Alp);
    cvt_kernel<<<MW4, 256>>>(Wk, Bhp, Blp);
    gemm_mma<<<gg, 256, GSM>>>(Ahp, Alp, Bhp, Blp, bk, Kp);

    cvt_kernel<<<MA4, 256>>>(v, Ahp, Alp);
    cvt_kernel<<<MW4, 256>>>(Wv, Bhp, Blp);
    gemm_mma<<<gg, 256, GSM>>>(Ahp, Alp, Bhp, Blp, bv, Vp);

    // attention operand planes
    cvt_scale_kernel<<<MA4, 256>>>(Qp, Qhp, Qlp);
    cvt_kernel<<<MA4, 256>>>(Kp, Khp, Klp);
    cvtT_kernel<<<dim3(S_/32, D_/32, B_), 256>>>(Vp, Vhp, Vlp);

    attn_mma<<<dim3(S_/128, H_, B_), 128, ASM>>>(Qhp, Qlp, Khp, Klp, Vhp, Vlp, mask, Cp);

    cvt_kernel<<<MA4, 256>>>(Cp, Ahp, Alp);
    cvt_kernel<<<MW4, 256>>>(Wo, Bhp, Blp);
    gemm_mma<<<gg, 256, GSM>>>(Ahp, Alp, Bhp, Blp, bo, out);
}

// round 8
// speedup vs baseline: 2.9127x; 1.0642x over previous
#include <cuda_runtime.h>
#include <cuda_bf16.h>
#include <cstdint>
#define B_ 2
#define S_ 2048
#define D_ 1024
#define H_ 16

__device__ float g_V[B_*S_*D_];                              // fp32 V projection
__device__ __nv_bfloat16 g_Ah[B_*S_*D_], g_Al[B_*S_*D_];     // act hi/lo (reused)
__device__ __nv_bfloat16 g_Bh[D_*D_],   g_Bl[D_*D_];         // wgt hi/lo
__device__ __nv_bfloat16 g_Qh[B_*S_*D_], g_Ql[B_*S_*D_];     // attn Q planes (scaled)
__device__ __nv_bfloat16 g_Kh[B_*S_*D_], g_Kl[B_*S_*D_];     // attn K planes
__device__ __nv_bfloat16 g_Vth[B_*S_*D_], g_Vtl[B_*S_*D_];   // V^T planes [b][h][d][s]
__device__ uint32_t g_mb[S_*S_/32];                          // mask bitplane

__device__ __forceinline__ uint32_t smem_u32(const void* p){
    uint32_t a; asm("{ .reg .u64 t; cvta.to.shared.u64 t, %1; cvt.u32.u64 %0, t; }":"=r"(a):"l"(p)); return a;
}
__device__ __forceinline__ void ldsm4(uint32_t* r, uint32_t a){
    asm volatile("ldmatrix.sync.aligned.m8n8.x4.shared.b16 {%0,%1,%2,%3}, [%4];"
        :"=r"(r[0]),"=r"(r[1]),"=r"(r[2]),"=r"(r[3]):"r"(a));
}
__device__ __forceinline__ void mmabf(float* c, const uint32_t* a, uint32_t b0, uint32_t b1){
    asm volatile("mma.sync.aligned.m16n8k16.row.col.f32.bf16.bf16.f32 "
        "{%0,%1,%2,%3}, {%4,%5,%6,%7}, {%8,%9}, {%0,%1,%2,%3};"
        :"+f"(c[0]),"+f"(c[1]),"+f"(c[2]),"+f"(c[3])
        :"r"(a[0]),"r"(a[1]),"r"(a[2]),"r"(a[3]),"r"(b0),"r"(b1));
}
__device__ __forceinline__ void cpa16(uint32_t d, const void* s){
    asm volatile("cp.async.cg.shared.global [%0], [%1], 16;"::"r"(d),"l"(s):"memory");
}
__device__ __forceinline__ uint32_t pk2(float a, float b){
    __nv_bfloat162 h = __floats2bfloat162_rn(a, b);
    return *reinterpret_cast<uint32_t*>(&h);
}
__device__ __forceinline__ float bflo(float v){
    return v - __bfloat162float(__float2bfloat16(v));
}
__device__ __forceinline__ float ex2(float x){
    float r; asm("ex2.approx.ftz.f32 %0, %1;":"=f"(r):"f"(x)); return r;
}

// ---------------- mask -> bitplane ----------------
__global__ void __launch_bounds__(256)
maskbits_kernel(const int* __restrict__ mask, uint32_t* __restrict__ bits)
{
    int i = blockIdx.x * 256 + threadIdx.x;
    uint32_t b = __ballot_sync(0xffffffffu, mask[i] != 0);
    if ((threadIdx.x & 31) == 0) bits[i >> 5] = b;
}

// ---------------- fp32 -> bf16 hi/lo planes ----------------
__global__ void __launch_bounds__(256)
cvt_kernel(const float* __restrict__ in, __nv_bfloat16* __restrict__ hi,
           __nv_bfloat16* __restrict__ lo)
{
    int i = blockIdx.x * 256 + threadIdx.x;
    float4 v = ((const float4*)in)[i];
    float a[4] = {v.x, v.y, v.z, v.w};
    unsigned short h[4], l[4];
    #pragma unroll
    for (int j = 0; j < 4; j++) {
        __nv_bfloat16 hb = __float2bfloat16(a[j]);
        h[j] = __bfloat16_as_ushort(hb);
        l[j] = __bfloat16_as_ushort(__float2bfloat16(a[j] - __bfloat162float(hb)));
    }
    ((uint2*)hi)[i] = make_uint2(h[0]|((uint32_t)h[1]<<16), h[2]|((uint32_t)h[3]<<16));
    ((uint2*)lo)[i] = make_uint2(l[0]|((uint32_t)l[1]<<16), l[2]|((uint32_t)l[3]<<16));
}
// V[b][s][h*64+d] -> Vt[b][h][d][s] hi/lo
__global__ void __launch_bounds__(256)
cvtT_kernel(const float* __restrict__ V, __nv_bfloat16* __restrict__ oh,
            __nv_bfloat16* __restrict__ ol)
{
    __shared__ float tile[32][33];
    const int s0 = blockIdx.x*32, d0 = blockIdx.y*32, b = blockIdx.z;
    const int tx = threadIdx.x & 31, ty = threadIdx.x >> 5;
    #pragma unroll
    for (int i = 0; i < 4; i++)
        tile[ty+8*i][tx] = V[((size_t)(b*S_+s0+ty+8*i))*D_ + d0+tx];
    __syncthreads();
    const int hh = d0 >> 6, dl = d0 & 63;
    #pragma unroll
    for (int i = 0; i < 4; i++) {
        int dr = ty + 8*i;
        float v = tile[tx][dr];
        __nv_bfloat16 hb = __float2bfloat16(v);
        size_t a = ((size_t)((b*H_+hh)*64 + dl + dr))*S_ + s0 + tx;
        oh[a] = hb; ol[a] = __float2bfloat16(v - __bfloat162float(hb));
    }
}

// ---------------------------------------------------------------------------
// HMMA bf16x3-split GEMM, 128x128 tile. Output either fp32 (outf) or
// bf16 hi/lo planes (oh/ol, scaled by oscale) — fused conversion.
// ---------------------------------------------------------------------------
static constexpr int PLN = 128 * 80;
static constexpr int STG = 4 * PLN;
static constexpr int GSM = 2 * STG;

__global__ void __launch_bounds__(256, 2)
gemm_mma(const __nv_bfloat16* __restrict__ Ah, const __nv_bfloat16* __restrict__ Al,
         const __nv_bfloat16* __restrict__ Bh, const __nv_bfloat16* __restrict__ Bl,
         const float* __restrict__ bias, float* __restrict__ outf,
         __nv_bfloat16* __restrict__ oh, __nv_bfloat16* __restrict__ ol, float oscale)
{
    extern __shared__ __align__(128) char sm[];
    const uint32_t sb = smem_u32(sm);
    const int t = threadIdx.x, lane = t & 31, w = t >> 5;
    const int bm = blockIdx.y * 128, bn = blockIdx.x * 128;
    const int mw = (w >> 1) * 32, nw = (w & 1) * 64;
    const int crow = t >> 1, coff = (t & 1) * 32;
    const char* gAh = (const char*)(Ah + (size_t)(bm + crow) * D_) + coff;
    const char* gAl = (const char*)(Al + (size_t)(bm + crow) * D_) + coff;
    const char* gBh = (const char*)(Bh + (size_t)(bn + crow) * D_) + coff;
    const char* gBl = (const char*)(Bl + (size_t)(bn + crow) * D_) + coff;
    const uint32_t dst0 = sb + crow * 80 + coff;

    float acc[2][8][4] = {};
    #define ISSUE(c, s) do { \
        uint32_t d = dst0 + (s) * STG; int go = (c) * 64; \
        cpa16(d,           gAh + go); cpa16(d + 16,           gAh + go + 16); \
        cpa16(d + PLN,     gAl + go); cpa16(d + PLN + 16,     gAl + go + 16); \
        cpa16(d + 2*PLN,   gBh + go); cpa16(d + 2*PLN + 16,   gBh + go + 16); \
        cpa16(d + 3*PLN,   gBl + go); cpa16(d + 3*PLN + 16,   gBl + go + 16); \
        asm volatile("cp.async.commit_group;" ::: "memory"); \
    } while (0)

    ISSUE(0, 0);
    const int NCH = D_ / 32;
    for (int c = 0; c < NCH; c++) {
        const int s = c & 1;
        if (c + 1 < NCH) { ISSUE(c + 1, s ^ 1); asm volatile("cp.async.wait_group 1;" ::: "memory"); }
        else             { asm volatile("cp.async.wait_group 0;" ::: "memory"); }
        __syncthreads();
        const uint32_t base = sb + s * STG;
        const int arow = mw + (lane & 15);
        const int brow = nw + (lane & 7) + ((lane >> 4) << 3);
        #pragma unroll
        for (int ks = 0; ks < 2; ks++) {
            const int acol = ks * 32 + ((lane >> 4) << 4);
            const int bcol = ks * 32 + (((lane >> 3) & 1) << 4);
            uint32_t ah[2][4], al[2][4];
            #pragma unroll
            for (int mi = 0; mi < 2; mi++) {
                uint32_t ad = base + (arow + mi * 16) * 80 + acol;
                ldsm4(ah[mi], ad); ldsm4(al[mi], ad + PLN);
            }
            #pragma unroll
            for (int nf = 0; nf < 4; nf++) {
                uint32_t bd = base + 2 * PLN + (brow + nf * 16) * 80 + bcol;
                uint32_t bh[4], bl[4];
                ldsm4(bh, bd); ldsm4(bl, bd + PLN);
                #pragma unroll
                for (int mi = 0; mi < 2; mi++) {
                    mmabf(acc[mi][2*nf],   ah[mi], bh[0], bh[1]);
                    mmabf(acc[mi][2*nf],   ah[mi], bl[0], bl[1]);
                    mmabf(acc[mi][2*nf],   al[mi], bh[0], bh[1]);
                    mmabf(acc[mi][2*nf+1], ah[mi], bh[2], bh[3]);
                    mmabf(acc[mi][2*nf+1], ah[mi], bl[2], bl[3]);
                    mmabf(acc[mi][2*nf+1], al[mi], bh[2], bh[3]);
                }
            }
        }
        __syncthreads();
    }
    #undef ISSUE
    #pragma unroll
    for (int mi = 0; mi < 2; mi++) {
        const int r0 = bm + mw + mi * 16 + (lane >> 2);
        #pragma unroll
        for (int nj = 0; nj < 8; nj++) {
            const int col = bn + nw + nj * 8 + (lane & 3) * 2;
            float2 bv = *(const float2*)&bias[col];
            float* c = acc[mi][nj];
            if (outf) {
                *(float2*)&outf[(size_t)r0 * D_ + col] = make_float2(c[0] + bv.x, c[1] + bv.y);
                *(float2*)&outf[(size_t)(r0 + 8) * D_ + col] = make_float2(c[2] + bv.x, c[3] + bv.y);
            } else {
                float v0 = (c[0] + bv.x) * oscale, v1 = (c[1] + bv.y) * oscale;
                float v2 = (c[2] + bv.x) * oscale, v3 = (c[3] + bv.y) * oscale;
                *(uint32_t*)&oh[(size_t)r0 * D_ + col]       = pk2(v0, v1);
                *(uint32_t*)&ol[(size_t)r0 * D_ + col]       = pk2(bflo(v0), bflo(v1));
                *(uint32_t*)&oh[(size_t)(r0 + 8) * D_ + col] = pk2(v2, v3);
                *(uint32_t*)&ol[(size_t)(r0 + 8) * D_ + col] = pk2(bflo(v2), bflo(v3));
            }
        }
    }
}

// ---------------------------------------------------------------------------
// HMMA flash attention, exp2-domain softmax, bitmask masking.
// Output written directly as bf16 hi/lo planes (input of the final GEMM).
// ---------------------------------------------------------------------------
static constexpr int KST  = 144;
static constexpr int KPL  = 64 * KST;
static constexpr int ASTG = 4 * KPL;
static constexpr int ASM  = 2 * ASTG;
static constexpr int QLO  = 128 * KST;

__global__ void __launch_bounds__(128, 2)
attn_mma(const __nv_bfloat16* __restrict__ Qh, const __nv_bfloat16* __restrict__ Ql,
         const __nv_bfloat16* __restrict__ Kh, const __nv_bfloat16* __restrict__ Kl,
         const __nv_bfloat16* __restrict__ Vth, const __nv_bfloat16* __restrict__ Vtl,
         const uint32_t* __restrict__ mb,
         __nv_bfloat16* __restrict__ ctxh, __nv_bfloat16* __restrict__ ctxl)
{
    extern __shared__ __align__(128) char sm[];
    const uint32_t sb = smem_u32(sm);
    const int t = threadIdx.x, lane = t & 31, w = t >> 5;
    const int b = blockIdx.z, h = blockIdx.y, q0 = blockIdx.x * 128;
    const int g = lane >> 2, qt = lane & 3;

    {   // stage Q tile (hi/lo), extract persistent A-frags
        const char* ph = (const char*)(Qh + ((size_t)(b*S_ + q0 + t))*D_ + h*64);
        const char* pl = (const char*)(Ql + ((size_t)(b*S_ + q0 + t))*D_ + h*64);
        uint32_t d = sb + t * KST;
        #pragma unroll
        for (int i = 0; i < 8; i++) { cpa16(d + i*16, ph + i*16); cpa16(d + QLO + i*16, pl + i*16); }
        asm volatile("cp.async.commit_group;" ::: "memory");
        asm volatile("cp.async.wait_group 0;" ::: "memory");
    }
    __syncthreads();
    uint32_t qfh[2][4][4], qfl[2][4][4];
    #pragma unroll
    for (int mi = 0; mi < 2; mi++)
        #pragma unroll
        for (int kc = 0; kc < 4; kc++) {
            uint32_t a = sb + (w*32 + mi*16 + (lane & 15)) * KST + kc*32 + ((lane >> 4) << 4);
            ldsm4(qfh[mi][kc], a);
            ldsm4(qfl[mi][kc], a + QLO);
        }
    __syncthreads();

    float o[2][8][4] = {};
    float m_i[2][2], l_i[2][2];
    #pragma unroll
    for (int mi = 0; mi < 2; mi++) { m_i[mi][0]=m_i[mi][1]=-1e30f; l_i[mi][0]=l_i[mi][1]=0.f; }

    const int krow = t >> 1, khalf = (t & 1) * 64;
    #define AISSUE(c, s) do { \
        uint32_t dd = sb + (s)*ASTG + krow*KST + khalf; \
        const char* pkh = (const char*)(Kh  + ((size_t)(b*S_ + (c)*64 + krow))*D_ + h*64) + khalf; \
        const char* pkl = (const char*)(Kl  + ((size_t)(b*S_ + (c)*64 + krow))*D_ + h*64) + khalf; \
        const char* pvh = (const char*)(Vth + ((size_t)((b*H_+h)*64 + krow))*S_ + (c)*64) + khalf; \
        const char* pvl = (const char*)(Vtl + ((size_t)((b*H_+h)*64 + krow))*S_ + (c)*64) + khalf; \
        _Pragma("unroll") for (int i = 0; i < 4; i++) { \
            cpa16(dd + i*16,         pkh + i*16); cpa16(dd + KPL + i*16,   pkl + i*16); \
            cpa16(dd + 2*KPL + i*16, pvh + i*16); cpa16(dd + 3*KPL + i*16, pvl + i*16); } \
        asm volatile("cp.async.commit_group;" ::: "memory"); \
    } while (0)

    AISSUE(0, 0);
    const int NT = S_ / 64;
    for (int c = 0; c < NT; c++) {
        const int s = c & 1;
        if (c + 1 < NT) { AISSUE(c + 1, s ^ 1); asm volatile("cp.async.wait_group 1;" ::: "memory"); }
        else            { asm volatile("cp.async.wait_group 0;" ::: "memory"); }
        __syncthreads();
        const uint32_t base = sb + s * ASTG;
        const int brow = (lane & 7) + ((lane >> 4) << 3);
        const int bcsel = ((lane >> 3) & 1) << 4;

        // prefetch mask bit-words (latency hidden behind S-MMAs)
        uint2 mwa[2], mwb[2];
        #pragma unroll
        for (int mi = 0; mi < 2; mi++) {
            const uint32_t* mp = mb + (size_t)(q0 + w*32 + mi*16 + g) * (S_/32) + c*2;
            mwa[mi] = *(const uint2*)mp;
            mwb[mi] = *(const uint2*)(mp + 8 * (S_/32));
        }

        // ---- S = Q K^T (3 split terms) ----
        float sacc[2][8][4] = {};
        #pragma unroll
        for (int kc = 0; kc < 4; kc++)
            #pragma unroll
            for (int np = 0; np < 4; np++) {
                uint32_t ad = base + (np*16 + brow) * KST + kc*32 + bcsel;
                uint32_t bh[4], bl[4];
                ldsm4(bh, ad); ldsm4(bl, ad + KPL);
                #pragma unroll
                for (int mi = 0; mi < 2; mi++) {
                    mmabf(sacc[mi][2*np],   qfh[mi][kc], bh[0], bh[1]);
                    mmabf(sacc[mi][2*np],   qfh[mi][kc], bl[0], bl[1]);
                    mmabf(sacc[mi][2*np],   qfl[mi][kc], bh[0], bh[1]);
                    mmabf(sacc[mi][2*np+1], qfh[mi][kc], bh[2], bh[3]);
                    mmabf(sacc[mi][2*np+1], qfh[mi][kc], bl[2], bl[3]);
                    mmabf(sacc[mi][2*np+1], qfl[mi][kc], bh[2], bh[3]);
                }
            }

        // ---- mask (bitplane) + online softmax (log2 domain) ----
        #pragma unroll
        for (int mi = 0; mi < 2; mi++) {
            uint32_t allm = mwa[mi].x & mwa[mi].y & mwb[mi].x & mwb[mi].y;
            if (allm != 0xFFFFFFFFu) {
                #pragma unroll
                for (int nf = 0; nf < 8; nf++) {
                    uint32_t w0 = (nf < 4) ? mwa[mi].x : mwa[mi].y;
                    uint32_t w1 = (nf < 4) ? mwb[mi].x : mwb[mi].y;
                    int sh = qt*2 + (nf & 3)*8;
                    if (!((w0 >> sh) & 1))     sacc[mi][nf][0] = -1e9f;
                    if (!((w0 >> (sh+1)) & 1)) sacc[mi][nf][1] = -1e9f;
                    if (!((w1 >> sh) & 1))     sacc[mi][nf][2] = -1e9f;
                    if (!((w1 >> (sh+1)) & 1)) sacc[mi][nf][3] = -1e9f;
                }
            }
            float mx0 = -1e30f, mx1 = -1e30f;
            #pragma unroll
            for (int nf = 0; nf < 8; nf++) {
                mx0 = fmaxf(mx0, fmaxf(sacc[mi][nf][0], sacc[mi][nf][1]));
                mx1 = fmaxf(mx1, fmaxf(sacc[mi][nf][2], sacc[mi][nf][3]));
            }
            mx0 = fmaxf(mx0, __shfl_xor_sync(0xffffffffu, mx0, 1));
            mx0 = fmaxf(mx0, __shfl_xor_sync(0xffffffffu, mx0, 2));
            mx1 = fmaxf(mx1, __shfl_xor_sync(0xffffffffu, mx1, 1));
            mx1 = fmaxf(mx1, __shfl_xor_sync(0xffffffffu, mx1, 2));
            float mn0 = fmaxf(m_i[mi][0], mx0), mn1 = fmaxf(m_i[mi][1], mx1);
            float al0 = ex2(m_i[mi][0] - mn0), al1 = ex2(m_i[mi][1] - mn1);
            float s0 = 0.f, s1 = 0.f;
            #pragma unroll
            for (int nf = 0; nf < 8; nf++) {
                sacc[mi][nf][0] = ex2(sacc[mi][nf][0] - mn0);
                sacc[mi][nf][1] = ex2(sacc[mi][nf][1] - mn0);
                sacc[mi][nf][2] = ex2(sacc[mi][nf][2] - mn1);
                sacc[mi][nf][3] = ex2(sacc[mi][nf][3] - mn1);
                s0 += sacc[mi][nf][0] + sacc[mi][nf][1];
                s1 += sacc[mi][nf][2] + sacc[mi][nf][3];
            }
            s0 += __shfl_xor_sync(0xffffffffu, s0, 1);
            s0 += __shfl_xor_sync(0xffffffffu, s0, 2);
            s1 += __shfl_xor_sync(0xffffffffu, s1, 1);
            s1 += __shfl_xor_sync(0xffffffffu, s1, 2);
            l_i[mi][0] = l_i[mi][0]*al0 + s0; m_i[mi][0] = mn0;
            l_i[mi][1] = l_i[mi][1]*al1 + s1; m_i[mi][1] = mn1;
            #pragma unroll
            for (int nf = 0; nf < 8; nf++) {
                o[mi][nf][0] *= al0; o[mi][nf][1] *= al0;
                o[mi][nf][2] *= al1; o[mi][nf][3] *= al1;
            }
        }

        // ---- O += P V (hi/lo repack, 3 split terms) ----
        #pragma unroll
        for (int kc = 0; kc < 4; kc++) {
            uint32_t ph[2][4], pl[2][4];
            #pragma unroll
            for (int mi = 0; mi < 2; mi++) {
                float* c0 = sacc[mi][2*kc];
                float* c1 = sacc[mi][2*kc+1];
                ph[mi][0] = pk2(c0[0], c0[1]); pl[mi][0] = pk2(bflo(c0[0]), bflo(c0[1]));
                ph[mi][1] = pk2(c0[2], c0[3]); pl[mi][1] = pk2(bflo(c0[2]), bflo(c0[3]));
                ph[mi][2] = pk2(c1[0], c1[1]); pl[mi][2] = pk2(bflo(c1[0]), bflo(c1[1]));
                ph[mi][3] = pk2(c1[2], c1[3]); pl[mi][3] = pk2(bflo(c1[2]), bflo(c1[3]));
            }
            #pragma unroll
            for (int np = 0; np < 4; np++) {
                uint32_t vd = base + 2*KPL + (np*16 + brow) * KST + kc*32 + bcsel;
                uint32_t vh[4], vl[4];
                ldsm4(vh, vd); ldsm4(vl, vd + KPL);
                #pragma unroll
                for (int mi = 0; mi < 2; mi++) {
                    mmabf(o[mi][2*np],   ph[mi], vh[0], vh[1]);
                    mmabf(o[mi][2*np],   ph[mi], vl[0], vl[1]);
                    mmabf(o[mi][2*np],   pl[mi], vh[0], vh[1]);
                    mmabf(o[mi][2*np+1], ph[mi], vh[2], vh[3]);
                    mmabf(o[mi][2*np+1], ph[mi], vl[2], vl[3]);
                    mmabf(o[mi][2*np+1], pl[mi], vh[2], vh[3]);
                }
            }
        }
        __syncthreads();
    }
    #undef AISSUE

    // epilogue: write context directly as bf16 hi/lo planes
    #pragma unroll
    for (int mi = 0; mi < 2; mi++) {
        const int r0 = q0 + w*32 + mi*16 + g;
        const float i0 = 1.f / l_i[mi][0], i1 = 1.f / l_i[mi][1];
        #pragma unroll
        for (int nf = 0; nf < 8; nf++) {
            const int col = h*64 + nf*8 + qt*2;
            float v0 = o[mi][nf][0]*i0, v1 = o[mi][nf][1]*i0;
            float v2 = o[mi][nf][2]*i1, v3 = o[mi][nf][3]*i1;
            *(uint32_t*)&ctxh[(size_t)(b*S_ + r0)*D_ + col]     = pk2(v0, v1);
            *(uint32_t*)&ctxl[(size_t)(b*S_ + r0)*D_ + col]     = pk2(bflo(v0), bflo(v1));
            *(uint32_t*)&ctxh[(size_t)(b*S_ + r0 + 8)*D_ + col] = pk2(v2, v3);
            *(uint32_t*)&ctxl[(size_t)(b*S_ + r0 + 8)*D_ + col] = pk2(bflo(v2), bflo(v3));
        }
    }
}

// ---------------------------------------------------------------------------
extern "C" void kernel_launch(void* const* d_in, const int* in_sizes, int n_in,
                              void* d_out, int out_size)
{
    const float* q  = (const float*)d_in[0];
    const float* k  = (const float*)d_in[1];
    const float* v  = (const float*)d_in[2];
    const int* mask = (const int*)  d_in[3];
    const float* Wq = (const float*)d_in[4];  const float* bq = (const float*)d_in[5];
    const float* Wk = (const float*)d_in[6];  const float* bk = (const float*)d_in[7];
    const float* Wv = (const float*)d_in[8];  const float* bv = (const float*)d_in[9];
    const float* Wo = (const float*)d_in[10]; const float* bo = (const float*)d_in[11];
    float* out = (float*)d_out;

    float *Vp;
    __nv_bfloat16 *Ahp, *Alp, *Bhp, *Blp, *Qhp, *Qlp, *Khp, *Klp, *Vhp, *Vlp;
    uint32_t* mbp;
    cudaGetSymbolAddress((void**)&Vp, g_V);
    cudaGetSymbolAddress((void**)&Ahp, g_Ah); cudaGetSymbolAddress((void**)&Alp, g_Al);
    cudaGetSymbolAddress((void**)&Bhp, g_Bh); cudaGetSymbolAddress((void**)&Blp, g_Bl);
    cudaGetSymbolAddress((void**)&Qhp, g_Qh); cudaGetSymbolAddress((void**)&Qlp, g_Ql);
    cudaGetSymbolAddress((void**)&Khp, g_Kh); cudaGetSymbolAddress((void**)&Klp, g_Kl);
    cudaGetSymbolAddress((void**)&Vhp, g_Vth); cudaGetSymbolAddress((void**)&Vlp, g_Vtl);
    cudaGetSymbolAddress((void**)&mbp, g_mb);

    const int MA4 = (B_ * S_ * D_) / 4 / 256;
    const int MW4 = (D_ * D_) / 4 / 256;
    dim3 gg(D_ / 128, (B_ * S_) / 128);
    const float QSC = 0.125f * 1.44269504088896f;   // fold log2(e) for exp2 softmax

    cudaFuncSetAttribute(gemm_mma, cudaFuncAttributeMaxDynamicSharedMemorySize, GSM);
    cudaFuncSetAttribute(attn_mma, cudaFuncAttributeMaxDynamicSharedMemorySize, ASM);

    maskbits_kernel<<<(S_*S_)/256, 256>>>(mask, mbp);

    cvt_kernel<<<MA4, 256>>>(q, Ahp, Alp);
    cvt_kernel<<<MW4, 256>>>(Wq, Bhp, Blp);
    gemm_mma<<<gg, 256, GSM>>>(Ahp, Alp, Bhp, Blp, bq, nullptr, Qhp, Qlp, QSC);

    cvt_kernel<<<MA4, 256>>>(k, Ahp, Alp);
    cvt_kernel<<<MW4, 256>>>(Wk, Bhp, Blp);
    gemm_mma<<<gg, 256, GSM>>>(Ahp, Alp, Bhp, Blp, bk, nullptr, Khp, Klp, 1.0f);

    cvt_kernel<<<MA4, 256>>>(v, Ahp, Alp);
    cvt_kernel<<<MW4, 256>>>(Wv, Bhp, Blp);
    gemm_mma<<<gg, 256, GSM>>>(Ahp, Alp, Bhp, Blp, bv, Vp, nullptr, nullptr, 1.0f);

    cvtT_kernel<<<dim3(S_/32, D_/32, B_), 256>>>(Vp, Vhp, Vlp);

    attn_mma<<<dim3(S_/128, H_, B_), 128, ASM>>>(Qhp, Qlp, Khp, Klp, Vhp, Vlp, mbp, Ahp, Alp);

    cvt_kernel<<<MW4, 256>>>(Wo, Bhp, Blp);
    gemm_mma<<<gg, 256, GSM>>>(Ahp, Alp, Bhp, Blp, bo, out, nullptr, nullptr, 1.0f);
}

// round 10
// speedup vs baseline: 3.4243x; 1.1756x over previous
#include <cuda_runtime.h>
#include <cuda_bf16.h>
#include <cuda_fp16.h>
#include <cstdint>
#define B_ 2
#define S_ 2048
#define D_ 1024
#define H_ 16
#define NACT (B_*S_*D_)

__device__ float g_V[NACT];                                   // fp32 V projection
__device__ __nv_bfloat16 g_Ah[3*NACT], g_Al[3*NACT];          // act hi/lo (3 slots; slot0 reused for ctx)
__device__ __nv_bfloat16 g_Bh[4*D_*D_], g_Bl[4*D_*D_];        // wgt hi/lo (Wq,Wk,Wv,Wo)
__device__ __nv_bfloat16 g_Qh[NACT], g_Ql[NACT];              // attn Q planes (scaled)
__device__ __nv_bfloat16 g_Kh[NACT], g_Kl[NACT];              // attn K planes
__device__ __half g_Vt[NACT];                                 // V^T fp16 [b][h][d][s]
__device__ uint32_t g_mb[S_*S_/32];                           // mask bitplane

__device__ __forceinline__ uint32_t smem_u32(const void* p){
    uint32_t a; asm("{ .reg .u64 t; cvta.to.shared.u64 t, %1; cvt.u32.u64 %0, t; }":"=r"(a):"l"(p)); return a;
}
__device__ __forceinline__ void ldsm4(uint32_t* r, uint32_t a){
    asm volatile("ldmatrix.sync.aligned.m8n8.x4.shared.b16 {%0,%1,%2,%3}, [%4];"
        :"=r"(r[0]),"=r"(r[1]),"=r"(r[2]),"=r"(r[3]):"r"(a));
}
__device__ __forceinline__ void mmabf(float* c, const uint32_t* a, uint32_t b0, uint32_t b1){
    asm volatile("mma.sync.aligned.m16n8k16.row.col.f32.bf16.bf16.f32 "
        "{%0,%1,%2,%3}, {%4,%5,%6,%7}, {%8,%9}, {%0,%1,%2,%3};"
        :"+f"(c[0]),"+f"(c[1]),"+f"(c[2]),"+f"(c[3])
        :"r"(a[0]),"r"(a[1]),"r"(a[2]),"r"(a[3]),"r"(b0),"r"(b1));
}
__device__ __forceinline__ void mmaf16(float* c, const uint32_t* a, uint32_t b0, uint32_t b1){
    asm volatile("mma.sync.aligned.m16n8k16.row.col.f32.f16.f16.f32 "
        "{%0,%1,%2,%3}, {%4,%5,%6,%7}, {%8,%9}, {%0,%1,%2,%3};"
        :"+f"(c[0]),"+f"(c[1]),"+f"(c[2]),"+f"(c[3])
        :"r"(a[0]),"r"(a[1]),"r"(a[2]),"r"(a[3]),"r"(b0),"r"(b1));
}
__device__ __forceinline__ void cpa16(uint32_t d, const void* s){
    asm volatile("cp.async.cg.shared.global [%0], [%1], 16;"::"r"(d),"l"(s):"memory");
}
__device__ __forceinline__ uint32_t pk2(float a, float b){
    __nv_bfloat162 h = __floats2bfloat162_rn(a, b);
    return *reinterpret_cast<uint32_t*>(&h);
}
__device__ __forceinline__ uint32_t pkh2(float a, float b){
    __half2 h = __floats2half2_rn(a, b);
    return *reinterpret_cast<uint32_t*>(&h);
}
__device__ __forceinline__ float bflo(float v){
    return v - __bfloat162float(__float2bfloat16(v));
}
__device__ __forceinline__ float ex2(float x){
    float r; asm("ex2.approx.ftz.f32 %0, %1;":"=f"(r):"f"(x)); return r;
}

// ---------------- mask -> bitplane ----------------
__global__ void __launch_bounds__(256)
maskbits_kernel(const int* __restrict__ mask, uint32_t* __restrict__ bits)
{
    int i = blockIdx.x * 256 + threadIdx.x;
    uint32_t b = __ballot_sync(0xffffffffu, mask[i] != 0);
    if ((threadIdx.x & 31) == 0) bits[i >> 5] = b;
}

// ---------------- z-batched fp32 -> bf16 hi/lo ----------------
// slot stride in uint2 units = nElem/4 (1 uint2 = 4 bf16)
__global__ void __launch_bounds__(256)
cvt3_kernel(const float* __restrict__ i0, const float* __restrict__ i1,
            const float* __restrict__ i2, __nv_bfloat16* __restrict__ hi,
            __nv_bfloat16* __restrict__ lo, int slot_u2)
{
    int z = blockIdx.y;
    const float* in = (z == 0) ? i0 : (z == 1) ? i1 : i2;
    int i = blockIdx.x * 256 + threadIdx.x;
    float4 v = ((const float4*)in)[i];
    float a[4] = {v.x, v.y, v.z, v.w};
    unsigned short h[4], l[4];
    #pragma unroll
    for (int j = 0; j < 4; j++) {
        __nv_bfloat16 hb = __float2bfloat16(a[j]);
        h[j] = __bfloat16_as_ushort(hb);
        l[j] = __bfloat16_as_ushort(__float2bfloat16(a[j] - __bfloat162float(hb)));
    }
    size_t o = (size_t)z * slot_u2 + i;
    ((uint2*)hi)[o] = make_uint2(h[0]|((uint32_t)h[1]<<16), h[2]|((uint32_t)h[3]<<16));
    ((uint2*)lo)[o] = make_uint2(l[0]|((uint32_t)l[1]<<16), l[2]|((uint32_t)l[3]<<16));
}
__global__ void __launch_bounds__(256)
cvt4_kernel(const float* __restrict__ i0, const float* __restrict__ i1,
            const float* __restrict__ i2, const float* __restrict__ i3,
            __nv_bfloat16* __restrict__ hi, __nv_bfloat16* __restrict__ lo, int slot_u2)
{
    int z = blockIdx.y;
    const float* in = (z == 0) ? i0 : (z == 1) ? i1 : (z == 2) ? i2 : i3;
    int i = blockIdx.x * 256 + threadIdx.x;
    float4 v = ((const float4*)in)[i];
    float a[4] = {v.x, v.y, v.z, v.w};
    unsigned short h[4], l[4];
    #pragma unroll
    for (int j = 0; j < 4; j++) {
        __nv_bfloat16 hb = __float2bfloat16(a[j]);
        h[j] = __bfloat16_as_ushort(hb);
        l[j] = __bfloat16_as_ushort(__float2bfloat16(a[j] - __bfloat162float(hb)));
    }
    size_t o = (size_t)z * slot_u2 + i;
    ((uint2*)hi)[o] = make_uint2(h[0]|((uint32_t)h[1]<<16), h[2]|((uint32_t)h[3]<<16));
    ((uint2*)lo)[o] = make_uint2(l[0]|((uint32_t)l[1]<<16), l[2]|((uint32_t)l[3]<<16));
}
// V[b][s][h*64+d] -> Vt[b][h][d][s] fp16
__global__ void __launch_bounds__(256)
cvtT_kernel(const float* __restrict__ V, __half* __restrict__ oh)
{
    __shared__ float tile[32][33];
    const int s0 = blockIdx.x*32, d0 = blockIdx.y*32, b = blockIdx.z;
    const int tx = threadIdx.x & 31, ty = threadIdx.x >> 5;
    #pragma unroll
    for (int i = 0; i < 4; i++)
        tile[ty+8*i][tx] = V[((size_t)(b*S_+s0+ty+8*i))*D_ + d0+tx];
    __syncthreads();
    const int hh = d0 >> 6, dl = d0 & 63;
    #pragma unroll
    for (int i = 0; i < 4; i++) {
        int dr = ty + 8*i;
        size_t a = ((size_t)((b*H_+hh)*64 + dl + dr))*S_ + s0 + tx;
        oh[a] = __float2half(tile[tx][dr]);
    }
}

// ---------------------------------------------------------------------------
// HMMA bf16x3-split GEMM core (macro-shared by both gemm kernels)
// ---------------------------------------------------------------------------
static constexpr int PLN = 128 * 80;
static constexpr int STG = 4 * PLN;
static constexpr int GSM = 2 * STG;

#define GEMM_CORE(gAh, gAl, gBh, gBl, acc) do { \
    const int crow = t >> 1, coff = (t & 1) * 32; \
    const char* pAh = (const char*)((gAh) + (size_t)(bm + crow) * D_) + coff; \
    const char* pAl = (const char*)((gAl) + (size_t)(bm + crow) * D_) + coff; \
    const char* pBh = (const char*)((gBh) + (size_t)(bn + crow) * D_) + coff; \
    const char* pBl = (const char*)((gBl) + (size_t)(bn + crow) * D_) + coff; \
    const uint32_t dst0 = sb + crow * 80 + coff; \
    const int NCH = D_ / 32; \
    for (int c = 0; c < NCH; c++) { \
        const int s = c & 1; \
        if (c == 0) { \
            uint32_t d = dst0; int go = 0; \
            cpa16(d, pAh+go); cpa16(d+16, pAh+go+16); \
            cpa16(d+PLN, pAl+go); cpa16(d+PLN+16, pAl+go+16); \
            cpa16(d+2*PLN, pBh+go); cpa16(d+2*PLN+16, pBh+go+16); \
            cpa16(d+3*PLN, pBl+go); cpa16(d+3*PLN+16, pBl+go+16); \
            asm volatile("cp.async.commit_group;" ::: "memory"); \
        } \
        if (c + 1 < NCH) { \
            uint32_t d = dst0 + (s^1) * STG; int go = (c+1) * 64; \
            cpa16(d, pAh+go); cpa16(d+16, pAh+go+16); \
            cpa16(d+PLN, pAl+go); cpa16(d+PLN+16, pAl+go+16); \
            cpa16(d+2*PLN, pBh+go); cpa16(d+2*PLN+16, pBh+go+16); \
            cpa16(d+3*PLN, pBl+go); cpa16(d+3*PLN+16, pBl+go+16); \
            asm volatile("cp.async.commit_group;" ::: "memory"); \
            asm volatile("cp.async.wait_group 1;" ::: "memory"); \
        } else { \
            asm volatile("cp.async.wait_group 0;" ::: "memory"); \
        } \
        __syncthreads(); \
        const uint32_t base = sb + s * STG; \
        const int arow = mw + (lane & 15); \
        const int brow = nw + (lane & 7) + ((lane >> 4) << 3); \
        _Pragma("unroll") \
        for (int ks = 0; ks < 2; ks++) { \
            const int acol = ks * 32 + ((lane >> 4) << 4); \
            const int bcol = ks * 32 + (((lane >> 3) & 1) << 4); \
            uint32_t ah[2][4], al[2][4]; \
            _Pragma("unroll") \
            for (int mi = 0; mi < 2; mi++) { \
                uint32_t ad = base + (arow + mi * 16) * 80 + acol; \
                ldsm4(ah[mi], ad); ldsm4(al[mi], ad + PLN); \
            } \
            _Pragma("unroll") \
            for (int nf = 0; nf < 4; nf++) { \
                uint32_t bd = base + 2 * PLN + (brow + nf * 16) * 80 + bcol; \
                uint32_t bh[4], bl[4]; \
                ldsm4(bh, bd); ldsm4(bl, bd + PLN); \
                _Pragma("unroll") \
                for (int mi = 0; mi < 2; mi++) { \
                    mmabf(acc[mi][2*nf],   ah[mi], bh[0], bh[1]); \
                    mmabf(acc[mi][2*nf],   ah[mi], bl[0], bl[1]); \
                    mmabf(acc[mi][2*nf],   al[mi], bh[0], bh[1]); \
                    mmabf(acc[mi][2*nf+1], ah[mi], bh[2], bh[3]); \
                    mmabf(acc[mi][2*nf+1], ah[mi], bl[2], bl[3]); \
                    mmabf(acc[mi][2*nf+1], al[mi], bh[2], bh[3]); \
                } \
            } \
        } \
        __syncthreads(); \
    } \
} while (0)

// z-batched QKV projection: z=0 -> Q planes (scaled), z=1 -> K planes, z=2 -> V fp32
__global__ void __launch_bounds__(256, 2)
gemm_qkv(const __nv_bfloat16* __restrict__ Ah3, const __nv_bfloat16* __restrict__ Al3,
         const __nv_bfloat16* __restrict__ Bh4, const __nv_bfloat16* __restrict__ Bl4,
         const float* __restrict__ bq, const float* __restrict__ bk,
         const float* __restrict__ bv, float* __restrict__ Vout,
         __nv_bfloat16* __restrict__ Qh, __nv_bfloat16* __restrict__ Ql,
         __nv_bfloat16* __restrict__ Kh, __nv_bfloat16* __restrict__ Kl, float qsc)
{
    extern __shared__ __align__(128) char sm[];
    const uint32_t sb = smem_u32(sm);
    const int t = threadIdx.x, lane = t & 31, w = t >> 5;
    const int bm = blockIdx.y * 128, bn = blockIdx.x * 128;
    const int mw = (w >> 1) * 32, nw = (w & 1) * 64;
    const int z = blockIdx.z;
    const __nv_bfloat16* Ah = Ah3 + (size_t)z * NACT;
    const __nv_bfloat16* Al = Al3 + (size_t)z * NACT;
    const __nv_bfloat16* Bh = Bh4 + (size_t)z * D_ * D_;
    const __nv_bfloat16* Bl = Bl4 + (size_t)z * D_ * D_;
    const float* bias = (z == 0) ? bq : (z == 1) ? bk : bv;

    float acc[2][8][4] = {};
    GEMM_CORE(Ah, Al, Bh, Bl, acc);

    const float osc = (z == 0) ? qsc : 1.0f;
    #pragma unroll
    for (int mi = 0; mi < 2; mi++) {
        const int r0 = bm + mw + mi * 16 + (lane >> 2);
        #pragma unroll
        for (int nj = 0; nj < 8; nj++) {
            const int col = bn + nw + nj * 8 + (lane & 3) * 2;
            float2 bv2 = *(const float2*)&bias[col];
            float* c = acc[mi][nj];
            if (z == 2) {
                *(float2*)&Vout[(size_t)r0 * D_ + col] = make_float2(c[0] + bv2.x, c[1] + bv2.y);
                *(float2*)&Vout[(size_t)(r0 + 8) * D_ + col] = make_float2(c[2] + bv2.x, c[3] + bv2.y);
            } else {
                __nv_bfloat16* oh = (z == 0) ? Qh : Kh;
                __nv_bfloat16* ol = (z == 0) ? Ql : Kl;
                float v0 = (c[0] + bv2.x) * osc, v1 = (c[1] + bv2.y) * osc;
                float v2 = (c[2] + bv2.x) * osc, v3 = (c[3] + bv2.y) * osc;
                *(uint32_t*)&oh[(size_t)r0 * D_ + col]       = pk2(v0, v1);
                *(uint32_t*)&ol[(size_t)r0 * D_ + col]       = pk2(bflo(v0), bflo(v1));
                *(uint32_t*)&oh[(size_t)(r0 + 8) * D_ + col] = pk2(v2, v3);
                *(uint32_t*)&ol[(size_t)(r0 + 8) * D_ + col] = pk2(bflo(v2), bflo(v3));
            }
        }
    }
}

// O projection: fp32 out
__global__ void __launch_bounds__(256, 2)
gemm_o(const __nv_bfloat16* __restrict__ Ah, const __nv_bfloat16* __restrict__ Al,
       const __nv_bfloat16* __restrict__ Bh, const __nv_bfloat16* __restrict__ Bl,
       const float* __restrict__ bias, float* __restrict__ outf)
{
    extern __shared__ __align__(128) char sm[];
    const uint32_t sb = smem_u32(sm);
    const int t = threadIdx.x, lane = t & 31, w = t >> 5;
    const int bm = blockIdx.y * 128, bn = blockIdx.x * 128;
    const int mw = (w >> 1) * 32, nw = (w & 1) * 64;

    float acc[2][8][4] = {};
    GEMM_CORE(Ah, Al, Bh, Bl, acc);

    #pragma unroll
    for (int mi = 0; mi < 2; mi++) {
        const int r0 = bm + mw + mi * 16 + (lane >> 2);
        #pragma unroll
        for (int nj = 0; nj < 8; nj++) {
            const int col = bn + nw + nj * 8 + (lane & 3) * 2;
            float2 bv2 = *(const float2*)&bias[col];
            float* c = acc[mi][nj];
            *(float2*)&outf[(size_t)r0 * D_ + col] = make_float2(c[0] + bv2.x, c[1] + bv2.y);
            *(float2*)&outf[(size_t)(r0 + 8) * D_ + col] = make_float2(c[2] + bv2.x, c[3] + bv2.y);
        }
    }
}

// ---------------------------------------------------------------------------
// HMMA flash attention: QK^T bf16x3, PV fp16x1 (P,V fp16), exp2 softmax,
// bitmask masking, bf16 hi/lo plane output.
// ---------------------------------------------------------------------------
static constexpr int KST  = 144;
static constexpr int KPL  = 64 * KST;      // 9216
static constexpr int ASTG = 3 * KPL;       // Kh, Kl, Vh(f16) = 27648
static constexpr int ASM  = 2 * ASTG;      // 55296
static constexpr int QLO  = 128 * KST;     // 18432

__global__ void __launch_bounds__(128, 2)
attn_mma(const __nv_bfloat16* __restrict__ Qh, const __nv_bfloat16* __restrict__ Ql,
         const __nv_bfloat16* __restrict__ Kh, const __nv_bfloat16* __restrict__ Kl,
         const __half* __restrict__ Vt, const uint32_t* __restrict__ mb,
         __nv_bfloat16* __restrict__ ctxh, __nv_bfloat16* __restrict__ ctxl)
{
    extern __shared__ __align__(128) char sm[];
    const uint32_t sb = smem_u32(sm);
    const int t = threadIdx.x, lane = t & 31, w = t >> 5;
    const int b = blockIdx.z, h = blockIdx.y, q0 = blockIdx.x * 128;
    const int g = lane >> 2, qt = lane & 3;

    {   // stage Q tile (hi/lo), extract persistent A-frags
        const char* ph = (const char*)(Qh + ((size_t)(b*S_ + q0 + t))*D_ + h*64);
        const char* pl = (const char*)(Ql + ((size_t)(b*S_ + q0 + t))*D_ + h*64);
        uint32_t d = sb + t * KST;
        #pragma unroll
        for (int i = 0; i < 8; i++) { cpa16(d + i*16, ph + i*16); cpa16(d + QLO + i*16, pl + i*16); }
        asm volatile("cp.async.commit_group;" ::: "memory");
        asm volatile("cp.async.wait_group 0;" ::: "memory");
    }
    __syncthreads();
    uint32_t qfh[2][4][4], qfl[2][4][4];
    #pragma unroll
    for (int mi = 0; mi < 2; mi++)
        #pragma unroll
        for (int kc = 0; kc < 4; kc++) {
            uint32_t a = sb + (w*32 + mi*16 + (lane & 15)) * KST + kc*32 + ((lane >> 4) << 4);
            ldsm4(qfh[mi][kc], a);
            ldsm4(qfl[mi][kc], a + QLO);
        }
    __syncthreads();

    float o[2][8][4] = {};
    float m_i[2][2], l_i[2][2];
    #pragma unroll
    for (int mi = 0; mi < 2; mi++) { m_i[mi][0]=m_i[mi][1]=-1e30f; l_i[mi][0]=l_i[mi][1]=0.f; }

    const int krow = t >> 1, khalf = (t & 1) * 64;
    #define AISSUE(c, s) do { \
        uint32_t dd = sb + (s)*ASTG + krow*KST + khalf; \
        const char* pkh = (const char*)(Kh + ((size_t)(b*S_ + (c)*64 + krow))*D_ + h*64) + khalf; \
        const char* pkl = (const char*)(Kl + ((size_t)(b*S_ + (c)*64 + krow))*D_ + h*64) + khalf; \
        const char* pvh = (const char*)(Vt + ((size_t)((b*H_+h)*64 + krow))*S_ + (c)*64) + khalf; \
        _Pragma("unroll") for (int i = 0; i < 4; i++) { \
            cpa16(dd + i*16,         pkh + i*16); \
            cpa16(dd + KPL + i*16,   pkl + i*16); \
            cpa16(dd + 2*KPL + i*16, pvh + i*16); } \
        asm volatile("cp.async.commit_group;" ::: "memory"); \
    } while (0)

    AISSUE(0, 0);
    const int NT = S_ / 64;
    for (int c = 0; c < NT; c++) {
        const int s = c & 1;
        if (c + 1 < NT) { AISSUE(c + 1, s ^ 1); asm volatile("cp.async.wait_group 1;" ::: "memory"); }
        else            { asm volatile("cp.async.wait_group 0;" ::: "memory"); }
        __syncthreads();
        const uint32_t base = sb + s * ASTG;
        const int brow = (lane & 7) + ((lane >> 4) << 3);
        const int bcsel = ((lane >> 3) & 1) << 4;

        uint2 mwa[2], mwb[2];
        #pragma unroll
        for (int mi = 0; mi < 2; mi++) {
            const uint32_t* mp = mb + (size_t)(q0 + w*32 + mi*16 + g) * (S_/32) + c*2;
            mwa[mi] = *(const uint2*)mp;
            mwb[mi] = *(const uint2*)(mp + 8 * (S_/32));
        }

        // ---- S = Q K^T (bf16, 3 split terms) ----
        float sacc[2][8][4] = {};
        #pragma unroll
        for (int kc = 0; kc < 4; kc++)
            #pragma unroll
            for (int np = 0; np < 4; np++) {
                uint32_t ad = base + (np*16 + brow) * KST + kc*32 + bcsel;
                uint32_t bh[4], bl[4];
                ldsm4(bh, ad); ldsm4(bl, ad + KPL);
                #pragma unroll
                for (int mi = 0; mi < 2; mi++) {
                    mmabf(sacc[mi][2*np],   qfh[mi][kc], bh[0], bh[1]);
                    mmabf(sacc[mi][2*np],   qfh[mi][kc], bl[0], bl[1]);
                    mmabf(sacc[mi][2*np],   qfl[mi][kc], bh[0], bh[1]);
                    mmabf(sacc[mi][2*np+1], qfh[mi][kc], bh[2], bh[3]);
                    mmabf(sacc[mi][2*np+1], qfh[mi][kc], bl[2], bl[3]);
                    mmabf(sacc[mi][2*np+1], qfl[mi][kc], bh[2], bh[3]);
                }
            }

        // ---- mask + online softmax (exp2 domain) ----
        #pragma unroll
        for (int mi = 0; mi < 2; mi++) {
            uint32_t allm = mwa[mi].x & mwa[mi].y & mwb[mi].x & mwb[mi].y;
            if (allm != 0xFFFFFFFFu) {
                #pragma unroll
                for (int nf = 0; nf < 8; nf++) {
                    uint32_t w0 = (nf < 4) ? mwa[mi].x : mwa[mi].y;
                    uint32_t w1 = (nf < 4) ? mwb[mi].x : mwb[mi].y;
                    int sh = qt*2 + (nf & 3)*8;
                    if (!((w0 >> sh) & 1))     sacc[mi][nf][0] = -1e9f;
                    if (!((w0 >> (sh+1)) & 1)) sacc[mi][nf][1] = -1e9f;
                    if (!((w1 >> sh) & 1))     sacc[mi][nf][2] = -1e9f;
                    if (!((w1 >> (sh+1)) & 1)) sacc[mi][nf][3] = -1e9f;
                }
            }
            float mx0 = -1e30f, mx1 = -1e30f;
            #pragma unroll
            for (int nf = 0; nf < 8; nf++) {
                mx0 = fmaxf(mx0, fmaxf(sacc[mi][nf][0], sacc[mi][nf][1]));
                mx1 = fmaxf(mx1, fmaxf(sacc[mi][nf][2], sacc[mi][nf][3]));
            }
            mx0 = fmaxf(mx0, __shfl_xor_sync(0xffffffffu, mx0, 1));
            mx0 = fmaxf(mx0, __shfl_xor_sync(0xffffffffu, mx0, 2));
            mx1 = fmaxf(mx1, __shfl_xor_sync(0xffffffffu, mx1, 1));
            mx1 = fmaxf(mx1, __shfl_xor_sync(0xffffffffu, mx1, 2));
            float mn0 = fmaxf(m_i[mi][0], mx0), mn1 = fmaxf(m_i[mi][1], mx1);
            float al0 = ex2(m_i[mi][0] - mn0), al1 = ex2(m_i[mi][1] - mn1);
            float s0 = 0.f, s1 = 0.f;
            #pragma unroll
            for (int nf = 0; nf < 8; nf++) {
                sacc[mi][nf][0] = ex2(sacc[mi][nf][0] - mn0);
                sacc[mi][nf][1] = ex2(sacc[mi][nf][1] - mn0);
                sacc[mi][nf][2] = ex2(sacc[mi][nf][2] - mn1);
                sacc[mi][nf][3] = ex2(sacc[mi][nf][3] - mn1);
                s0 += sacc[mi][nf][0] + sacc[mi][nf][1];
                s1 += sacc[mi][nf][2] + sacc[mi][nf][3];
            }
            s0 += __shfl_xor_sync(0xffffffffu, s0, 1);
            s0 += __shfl_xor_sync(0xffffffffu, s0, 2);
            s1 += __shfl_xor_sync(0xffffffffu, s1, 1);
            s1 += __shfl_xor_sync(0xffffffffu, s1, 2);
            l_i[mi][0] = l_i[mi][0]*al0 + s0; m_i[mi][0] = mn0;
            l_i[mi][1] = l_i[mi][1]*al1 + s1; m_i[mi][1] = mn1;
            #pragma unroll
            for (int nf = 0; nf < 8; nf++) {
                o[mi][nf][0] *= al0; o[mi][nf][1] *= al0;
                o[mi][nf][2] *= al1; o[mi][nf][3] *= al1;
            }
        }

        // ---- O += P V (fp16 single term) ----
        #pragma unroll
        for (int kc = 0; kc < 4; kc++) {
            uint32_t ph[2][4];
            #pragma unroll
            for (int mi = 0; mi < 2; mi++) {
                float* c0 = sacc[mi][2*kc];
                float* c1 = sacc[mi][2*kc+1];
                ph[mi][0] = pkh2(c0[0], c0[1]); ph[mi][1] = pkh2(c0[2], c0[3]);
                ph[mi][2] = pkh2(c1[0], c1[1]); ph[mi][3] = pkh2(c1[2], c1[3]);
            }
            #pragma unroll
            for (int np = 0; np < 4; np++) {
                uint32_t vd = base + 2*KPL + (np*16 + brow) * KST + kc*32 + bcsel;
                uint32_t vh[4];
                ldsm4(vh, vd);
                #pragma unroll
                for (int mi = 0; mi < 2; mi++) {
                    mmaf16(o[mi][2*np],   ph[mi], vh[0], vh[1]);
                    mmaf16(o[mi][2*np+1], ph[mi], vh[2], vh[3]);
                }
            }
        }
        __syncthreads();
    }
    #undef AISSUE

    #pragma unroll
    for (int mi = 0; mi < 2; mi++) {
        const int r0 = q0 + w*32 + mi*16 + g;
        const float i0 = 1.f / l_i[mi][0], i1 = 1.f / l_i[mi][1];
        #pragma unroll
        for (int nf = 0; nf < 8; nf++) {
            const int col = h*64 + nf*8 + qt*2;
            float v0 = o[mi][nf][0]*i0, v1 = o[mi][nf][1]*i0;
            float v2 = o[mi][nf][2]*i1, v3 = o[mi][nf][3]*i1;
            *(uint32_t*)&ctxh[(size_t)(b*S_ + r0)*D_ + col]     = pk2(v0, v1);
            *(uint32_t*)&ctxl[(size_t)(b*S_ + r0)*D_ + col]     = pk2(bflo(v0), bflo(v1));
            *(uint32_t*)&ctxh[(size_t)(b*S_ + r0 + 8)*D_ + col] = pk2(v2, v3);
            *(uint32_t*)&ctxl[(size_t)(b*S_ + r0 + 8)*D_ + col] = pk2(bflo(v2), bflo(v3));
        }
    }
}

// ---------------------------------------------------------------------------
extern "C" void kernel_launch(void* const* d_in, const int* in_sizes, int n_in,
                              void* d_out, int out_size)
{
    const float* q  = (const float*)d_in[0];
    const float* k  = (const float*)d_in[1];
    const float* v  = (const float*)d_in[2];
    const int* mask = (const int*)  d_in[3];
    const float* Wq = (const float*)d_in[4];  const float* bq = (const float*)d_in[5];
    const float* Wk = (const float*)d_in[6];  const float* bk = (const float*)d_in[7];
    const float* Wv = (const float*)d_in[8];  const float* bv = (const float*)d_in[9];
    const float* Wo = (const float*)d_in[10]; const float* bo = (const float*)d_in[11];
    float* out = (float*)d_out;

    float *Vp;
    __nv_bfloat16 *Ahp, *Alp, *Bhp, *Blp, *Qhp, *Qlp, *Khp, *Klp;
    __half* Vtp;
    uint32_t* mbp;
    cudaGetSymbolAddress((void**)&Vp, g_V);
    cudaGetSymbolAddress((void**)&Ahp, g_Ah); cudaGetSymbolAddress((void**)&Alp, g_Al);
    cudaGetSymbolAddress((void**)&Bhp, g_Bh); cudaGetSymbolAddress((void**)&Blp, g_Bl);
    cudaGetSymbolAddress((void**)&Qhp, g_Qh); cudaGetSymbolAddress((void**)&Qlp, g_Ql);
    cudaGetSymbolAddress((void**)&Khp, g_Kh); cudaGetSymbolAddress((void**)&Klp, g_Kl);
    cudaGetSymbolAddress((void**)&Vtp, g_Vt);
    cudaGetSymbolAddress((void**)&mbp, g_mb);

    const int MA4 = NACT / 4 / 256;
    const int MW4 = (D_ * D_) / 4 / 256;
    const float QSC = 0.125f * 1.44269504088896f;

    cudaFuncSetAttribute(gemm_qkv, cudaFuncAttributeMaxDynamicSharedMemorySize, GSM);
    cudaFuncSetAttribute(gemm_o,   cudaFuncAttributeMaxDynamicSharedMemorySize, GSM);
    cudaFuncSetAttribute(attn_mma, cudaFuncAttributeMaxDynamicSharedMemorySize, ASM);

    maskbits_kernel<<<(S_*S_)/256, 256>>>(mask, mbp);
    // slot stride in uint2 units: NACT bf16 per slot = NACT/4 uint2
    cvt3_kernel<<<dim3(MA4, 3), 256>>>(q, k, v, Ahp, Alp, NACT / 4);
    cvt4_kernel<<<dim3(MW4, 4), 256>>>(Wq, Wk, Wv, Wo, Bhp, Blp, (D_ * D_) / 4);

    gemm_qkv<<<dim3(D_/128, (B_*S_)/128, 3), 256, GSM>>>(
        Ahp, Alp, Bhp, Blp, bq, bk, bv, Vp, Qhp, Qlp, Khp, Klp, QSC);

    cvtT_kernel<<<dim3(S_/32, D_/32, B_), 256>>>(Vp, Vtp);

    attn_mma<<<dim3(S_/128, H_, B_), 128, ASM>>>(Qhp, Qlp, Khp, Klp, Vtp, mbp, Ahp, Alp);

    gemm_o<<<dim3(D_/128, (B_*S_)/128), 256, GSM>>>(
        Ahp, Alp, Bhp + (size_t)3*D_*D_, Blp + (size_t)3*D_*D_, bo, out);
}

// round 11
// speedup vs baseline: 3.4261x; 1.0005x over previous
#include <cuda_runtime.h>
#include <cuda_bf16.h>
#include <cuda_fp16.h>
#include <cstdint>
#define B_ 2
#define S_ 2048
#define D_ 1024
#define H_ 16
#define NACT (B_*S_*D_)

__device__ float g_V[NACT];                                   // fp32 V projection
__device__ __nv_bfloat16 g_Ah[3*NACT], g_Al[3*NACT];          // act hi/lo (3 slots; slot0 reused for ctx)
__device__ __nv_bfloat16 g_Bh[4*D_*D_], g_Bl[4*D_*D_];        // wgt hi/lo (Wq,Wk,Wv,Wo)
__device__ __nv_bfloat16 g_Qh[NACT], g_Ql[NACT];              // attn Q planes (scaled)
__device__ __nv_bfloat16 g_Kh[NACT], g_Kl[NACT];              // attn K planes
__device__ __half g_Vt[NACT];                                 // V^T fp16 [b][h][d][s]
__device__ uint32_t g_mb[S_*S_/32];                           // mask bitplane

__device__ __forceinline__ uint32_t smem_u32(const void* p){
    uint32_t a; asm("{ .reg .u64 t; cvta.to.shared.u64 t, %1; cvt.u32.u64 %0, t; }":"=r"(a):"l"(p)); return a;
}
__device__ __forceinline__ void ldsm4(uint32_t* r, uint32_t a){
    asm volatile("ldmatrix.sync.aligned.m8n8.x4.shared.b16 {%0,%1,%2,%3}, [%4];"
        :"=r"(r[0]),"=r"(r[1]),"=r"(r[2]),"=r"(r[3]):"r"(a));
}
__device__ __forceinline__ void mmabf(float* c, const uint32_t* a, uint32_t b0, uint32_t b1){
    asm volatile("mma.sync.aligned.m16n8k16.row.col.f32.bf16.bf16.f32 "
        "{%0,%1,%2,%3}, {%4,%5,%6,%7}, {%8,%9}, {%0,%1,%2,%3};"
        :"+f"(c[0]),"+f"(c[1]),"+f"(c[2]),"+f"(c[3])
        :"r"(a[0]),"r"(a[1]),"r"(a[2]),"r"(a[3]),"r"(b0),"r"(b1));
}
__device__ __forceinline__ void mmaf16(float* c, const uint32_t* a, uint32_t b0, uint32_t b1){
    asm volatile("mma.sync.aligned.m16n8k16.row.col.f32.f16.f16.f32 "
        "{%0,%1,%2,%3}, {%4,%5,%6,%7}, {%8,%9}, {%0,%1,%2,%3};"
        :"+f"(c[0]),"+f"(c[1]),"+f"(c[2]),"+f"(c[3])
        :"r"(a[0]),"r"(a[1]),"r"(a[2]),"r"(a[3]),"r"(b0),"r"(b1));
}
__device__ __forceinline__ void cpa16(uint32_t d, const void* s){
    asm volatile("cp.async.cg.shared.global [%0], [%1], 16;"::"r"(d),"l"(s):"memory");
}
__device__ __forceinline__ uint32_t pk2(float a, float b){
    __nv_bfloat162 h = __floats2bfloat162_rn(a, b);
    return *reinterpret_cast<uint32_t*>(&h);
}
__device__ __forceinline__ uint32_t pkh2(float a, float b){
    __half2 h = __floats2half2_rn(a, b);
    return *reinterpret_cast<uint32_t*>(&h);
}
__device__ __forceinline__ float bflo(float v){
    return v - __bfloat162float(__float2bfloat16(v));
}
__device__ __forceinline__ float ex2(float x){
    float r; asm("ex2.approx.ftz.f32 %0, %1;":"=f"(r):"f"(x)); return r;
}

// ---------------- mask -> bitplane ----------------
__global__ void __launch_bounds__(256)
maskbits_kernel(const int* __restrict__ mask, uint32_t* __restrict__ bits)
{
    int i = blockIdx.x * 256 + threadIdx.x;
    uint32_t b = __ballot_sync(0xffffffffu, mask[i] != 0);
    if ((threadIdx.x & 31) == 0) bits[i >> 5] = b;
}

// ---------------- z-batched fp32 -> bf16 hi/lo ----------------
// slot stride in uint2 units = nElem/4 (1 uint2 = 4 bf16)
__global__ void __launch_bounds__(256)
cvt3_kernel(const float* __restrict__ i0, const float* __restrict__ i1,
            const float* __restrict__ i2, __nv_bfloat16* __restrict__ hi,
            __nv_bfloat16* __restrict__ lo, int slot_u2)
{
    int z = blockIdx.y;
    const float* in = (z == 0) ? i0 : (z == 1) ? i1 : i2;
    int i = blockIdx.x * 256 + threadIdx.x;
    float4 v = ((const float4*)in)[i];
    float a[4] = {v.x, v.y, v.z, v.w};
    unsigned short h[4], l[4];
    #pragma unroll
    for (int j = 0; j < 4; j++) {
        __nv_bfloat16 hb = __float2bfloat16(a[j]);
        h[j] = __bfloat16_as_ushort(hb);
        l[j] = __bfloat16_as_ushort(__float2bfloat16(a[j] - __bfloat162float(hb)));
    }
    size_t o = (size_t)z * slot_u2 + i;
    ((uint2*)hi)[o] = make_uint2(h[0]|((uint32_t)h[1]<<16), h[2]|((uint32_t)h[3]<<16));
    ((uint2*)lo)[o] = make_uint2(l[0]|((uint32_t)l[1]<<16), l[2]|((uint32_t)l[3]<<16));
}
__global__ void __launch_bounds__(256)
cvt4_kernel(const float* __restrict__ i0, const float* __restrict__ i1,
            const float* __restrict__ i2, const float* __restrict__ i3,
            __nv_bfloat16* __restrict__ hi, __nv_bfloat16* __restrict__ lo, int slot_u2)
{
    int z = blockIdx.y;
    const float* in = (z == 0) ? i0 : (z == 1) ? i1 : (z == 2) ? i2 : i3;
    int i = blockIdx.x * 256 + threadIdx.x;
    float4 v = ((const float4*)in)[i];
    float a[4] = {v.x, v.y, v.z, v.w};
    unsigned short h[4], l[4];
    #pragma unroll
    for (int j = 0; j < 4; j++) {
        __nv_bfloat16 hb = __float2bfloat16(a[j]);
        h[j] = __bfloat16_as_ushort(hb);
        l[j] = __bfloat16_as_ushort(__float2bfloat16(a[j] - __bfloat162float(hb)));
    }
    size_t o = (size_t)z * slot_u2 + i;
    ((uint2*)hi)[o] = make_uint2(h[0]|((uint32_t)h[1]<<16), h[2]|((uint32_t)h[3]<<16));
    ((uint2*)lo)[o] = make_uint2(l[0]|((uint32_t)l[1]<<16), l[2]|((uint32_t)l[3]<<16));
}
// V[b][s][h*64+d] -> Vt[b][h][d][s] fp16
__global__ void __launch_bounds__(256)
cvtT_kernel(const float* __restrict__ V, __half* __restrict__ oh)
{
    __shared__ float tile[32][33];
    const int s0 = blockIdx.x*32, d0 = blockIdx.y*32, b = blockIdx.z;
    const int tx = threadIdx.x & 31, ty = threadIdx.x >> 5;
    #pragma unroll
    for (int i = 0; i < 4; i++)
        tile[ty+8*i][tx] = V[((size_t)(b*S_+s0+ty+8*i))*D_ + d0+tx];
    __syncthreads();
    const int hh = d0 >> 6, dl = d0 & 63;
    #pragma unroll
    for (int i = 0; i < 4; i++) {
        int dr = ty + 8*i;
        size_t a = ((size_t)((b*H_+hh)*64 + dl + dr))*S_ + s0 + tx;
        oh[a] = __float2half(tile[tx][dr]);
    }
}

// ---------------------------------------------------------------------------
// HMMA bf16x3-split GEMM core (macro-shared by both gemm kernels)
// ---------------------------------------------------------------------------
static constexpr int PLN = 128 * 80;
static constexpr int STG = 4 * PLN;
static constexpr int GSM = 2 * STG;

#define GEMM_CORE(gAh, gAl, gBh, gBl, acc) do { \
    const int crow = t >> 1, coff = (t & 1) * 32; \
    const char* pAh = (const char*)((gAh) + (size_t)(bm + crow) * D_) + coff; \
    const char* pAl = (const char*)((gAl) + (size_t)(bm + crow) * D_) + coff; \
    const char* pBh = (const char*)((gBh) + (size_t)(bn + crow) * D_) + coff; \
    const char* pBl = (const char*)((gBl) + (size_t)(bn + crow) * D_) + coff; \
    const uint32_t dst0 = sb + crow * 80 + coff; \
    const int NCH = D_ / 32; \
    for (int c = 0; c < NCH; c++) { \
        const int s = c & 1; \
        if (c == 0) { \
            uint32_t d = dst0; int go = 0; \
            cpa16(d, pAh+go); cpa16(d+16, pAh+go+16); \
            cpa16(d+PLN, pAl+go); cpa16(d+PLN+16, pAl+go+16); \
            cpa16(d+2*PLN, pBh+go); cpa16(d+2*PLN+16, pBh+go+16); \
            cpa16(d+3*PLN, pBl+go); cpa16(d+3*PLN+16, pBl+go+16); \
            asm volatile("cp.async.commit_group;" ::: "memory"); \
        } \
        if (c + 1 < NCH) { \
            uint32_t d = dst0 + (s^1) * STG; int go = (c+1) * 64; \
            cpa16(d, pAh+go); cpa16(d+16, pAh+go+16); \
            cpa16(d+PLN, pAl+go); cpa16(d+PLN+16, pAl+go+16); \
            cpa16(d+2*PLN, pBh+go); cpa16(d+2*PLN+16, pBh+go+16); \
            cpa16(d+3*PLN, pBl+go); cpa16(d+3*PLN+16, pBl+go+16); \
            asm volatile("cp.async.commit_group;" ::: "memory"); \
            asm volatile("cp.async.wait_group 1;" ::: "memory"); \
        } else { \
            asm volatile("cp.async.wait_group 0;" ::: "memory"); \
        } \
        __syncthreads(); \
        const uint32_t base = sb + s * STG; \
        const int arow = mw + (lane & 15); \
        const int brow = nw + (lane & 7) + ((lane >> 4) << 3); \
        _Pragma("unroll") \
        for (int ks = 0; ks < 2; ks++) { \
            const int acol = ks * 32 + ((lane >> 4) << 4); \
            const int bcol = ks * 32 + (((lane >> 3) & 1) << 4); \
            uint32_t ah[2][4], al[2][4]; \
            _Pragma("unroll") \
            for (int mi = 0; mi < 2; mi++) { \
                uint32_t ad = base + (arow + mi * 16) * 80 + acol; \
                ldsm4(ah[mi], ad); ldsm4(al[mi], ad + PLN); \
            } \
            _Pragma("unroll") \
            for (int nf = 0; nf < 4; nf++) { \
                uint32_t bd = base + 2 * PLN + (brow + nf * 16) * 80 + bcol; \
                uint32_t bh[4], bl[4]; \
                ldsm4(bh, bd); ldsm4(bl, bd + PLN); \
                _Pragma("unroll") \
                for (int mi = 0; mi < 2; mi++) { \
                    mmabf(acc[mi][2*nf],   ah[mi], bh[0], bh[1]); \
                    mmabf(acc[mi][2*nf],   ah[mi], bl[0], bl[1]); \
                    mmabf(acc[mi][2*nf],   al[mi], bh[0], bh[1]); \
                    mmabf(acc[mi][2*nf+1], ah[mi], bh[2], bh[3]); \
                    mmabf(acc[mi][2*nf+1], ah[mi], bl[2], bl[3]); \
                    mmabf(acc[mi][2*nf+1], al[mi], bh[2], bh[3]); \
                } \
            } \
        } \
        __syncthreads(); \
    } \
} while (0)

// z-batched QKV projection: z=0 -> Q planes (scaled), z=1 -> K planes, z=2 -> V fp32
__global__ void __launch_bounds__(256, 2)
gemm_qkv(const __nv_bfloat16* __restrict__ Ah3, const __nv_bfloat16* __restrict__ Al3,
         const __nv_bfloat16* __restrict__ Bh4, const __nv_bfloat16* __restrict__ Bl4,
         const float* __restrict__ bq, const float* __restrict__ bk,
         const float* __restrict__ bv, float* __restrict__ Vout,
         __nv_bfloat16* __restrict__ Qh, __nv_bfloat16* __restrict__ Ql,
         __nv_bfloat16* __restrict__ Kh, __nv_bfloat16* __restrict__ Kl, float qsc)
{
    extern __shared__ __align__(128) char sm[];
    const uint32_t sb = smem_u32(sm);
    const int t = threadIdx.x, lane = t & 31, w = t >> 5;
    const int bm = blockIdx.y * 128, bn = blockIdx.x * 128;
    const int mw = (w >> 1) * 32, nw = (w & 1) * 64;
    const int z = blockIdx.z;
    const __nv_bfloat16* Ah = Ah3 + (size_t)z * NACT;
    const __nv_bfloat16* Al = Al3 + (size_t)z * NACT;
    const __nv_bfloat16* Bh = Bh4 + (size_t)z * D_ * D_;
    const __nv_bfloat16* Bl = Bl4 + (size_t)z * D_ * D_;
    const float* bias = (z == 0) ? bq : (z == 1) ? bk : bv;

    float acc[2][8][4] = {};
    GEMM_CORE(Ah, Al, Bh, Bl, acc);

    const float osc = (z == 0) ? qsc : 1.0f;
    #pragma unroll
    for (int mi = 0; mi < 2; mi++) {
        const int r0 = bm + mw + mi * 16 + (lane >> 2);
        #pragma unroll
        for (int nj = 0; nj < 8; nj++) {
            const int col = bn + nw + nj * 8 + (lane & 3) * 2;
            float2 bv2 = *(const float2*)&bias[col];
            float* c = acc[mi][nj];
            if (z == 2) {
                *(float2*)&Vout[(size_t)r0 * D_ + col] = make_float2(c[0] + bv2.x, c[1] + bv2.y);
                *(float2*)&Vout[(size_t)(r0 + 8) * D_ + col] = make_float2(c[2] + bv2.x, c[3] + bv2.y);
            } else {
                __nv_bfloat16* oh = (z == 0) ? Qh : Kh;
                __nv_bfloat16* ol = (z == 0) ? Ql : Kl;
                float v0 = (c[0] + bv2.x) * osc, v1 = (c[1] + bv2.y) * osc;
                float v2 = (c[2] + bv2.x) * osc, v3 = (c[3] + bv2.y) * osc;
                *(uint32_t*)&oh[(size_t)r0 * D_ + col]       = pk2(v0, v1);
                *(uint32_t*)&ol[(size_t)r0 * D_ + col]       = pk2(bflo(v0), bflo(v1));
                *(uint32_t*)&oh[(size_t)(r0 + 8) * D_ + col] = pk2(v2, v3);
                *(uint32_t*)&ol[(size_t)(r0 + 8) * D_ + col] = pk2(bflo(v2), bflo(v3));
            }
        }
    }
}

// O projection: fp32 out
__global__ void __launch_bounds__(256, 2)
gemm_o(const __nv_bfloat16* __restrict__ Ah, const __nv_bfloat16* __restrict__ Al,
       const __nv_bfloat16* __restrict__ Bh, const __nv_bfloat16* __restrict__ Bl,
       const float* __restrict__ bias, float* __restrict__ outf)
{
    extern __shared__ __align__(128) char sm[];
    const uint32_t sb = smem_u32(sm);
    const int t = threadIdx.x, lane = t & 31, w = t >> 5;
    const int bm = blockIdx.y * 128, bn = blockIdx.x * 128;
    const int mw = (w >> 1) * 32, nw = (w & 1) * 64;

    float acc[2][8][4] = {};
    GEMM_CORE(Ah, Al, Bh, Bl, acc);

    #pragma unroll
    for (int mi = 0; mi < 2; mi++) {
        const int r0 = bm + mw + mi * 16 + (lane >> 2);
        #pragma unroll
        for (int nj = 0; nj < 8; nj++) {
            const int col = bn + nw + nj * 8 + (lane & 3) * 2;
            float2 bv2 = *(const float2*)&bias[col];
            float* c = acc[mi][nj];
            *(float2*)&outf[(size_t)r0 * D_ + col] = make_float2(c[0] + bv2.x, c[1] + bv2.y);
            *(float2*)&outf[(size_t)(r0 + 8) * D_ + col] = make_float2(c[2] + bv2.x, c[3] + bv2.y);
        }
    }
}

// ---------------------------------------------------------------------------
// HMMA flash attention: QK^T bf16x3, PV fp16x1 (P,V fp16), exp2 softmax,
// bitmask masking, bf16 hi/lo plane output.
// ---------------------------------------------------------------------------
static constexpr int KST  = 144;
static constexpr int KPL  = 64 * KST;      // 9216
static constexpr int ASTG = 3 * KPL;       // Kh, Kl, Vh(f16) = 27648
static constexpr int ASM  = 2 * ASTG;      // 55296
static constexpr int QLO  = 128 * KST;     // 18432

__global__ void __launch_bounds__(128, 2)
attn_mma(const __nv_bfloat16* __restrict__ Qh, const __nv_bfloat16* __restrict__ Ql,
         const __nv_bfloat16* __restrict__ Kh, const __nv_bfloat16* __restrict__ Kl,
         const __half* __restrict__ Vt, const uint32_t* __restrict__ mb,
         __nv_bfloat16* __restrict__ ctxh, __nv_bfloat16* __restrict__ ctxl)
{
    extern __shared__ __align__(128) char sm[];
    const uint32_t sb = smem_u32(sm);
    const int t = threadIdx.x, lane = t & 31, w = t >> 5;
    const int b = blockIdx.z, h = blockIdx.y, q0 = blockIdx.x * 128;
    const int g = lane >> 2, qt = lane & 3;

    {   // stage Q tile (hi/lo), extract persistent A-frags
        const char* ph = (const char*)(Qh + ((size_t)(b*S_ + q0 + t))*D_ + h*64);
        const char* pl = (const char*)(Ql + ((size_t)(b*S_ + q0 + t))*D_ + h*64);
        uint32_t d = sb + t * KST;
        #pragma unroll
        for (int i = 0; i < 8; i++) { cpa16(d + i*16, ph + i*16); cpa16(d + QLO + i*16, pl + i*16); }
        asm volatile("cp.async.commit_group;" ::: "memory");
        asm volatile("cp.async.wait_group 0;" ::: "memory");
    }
    __syncthreads();
    uint32_t qfh[2][4][4], qfl[2][4][4];
    #pragma unroll
    for (int mi = 0; mi < 2; mi++)
        #pragma unroll
        for (int kc = 0; kc < 4; kc++) {
            uint32_t a = sb + (w*32 + mi*16 + (lane & 15)) * KST + kc*32 + ((lane >> 4) << 4);
            ldsm4(qfh[mi][kc], a);
            ldsm4(qfl[mi][kc], a + QLO);
        }
    __syncthreads();

    float o[2][8][4] = {};
    float m_i[2][2], l_i[2][2];
    #pragma unroll
    for (int mi = 0; mi < 2; mi++) { m_i[mi][0]=m_i[mi][1]=-1e30f; l_i[mi][0]=l_i[mi][1]=0.f; }

    const int krow = t >> 1, khalf = (t & 1) * 64;
    #define AISSUE(c, s) do { \
        uint32_t dd = sb + (s)*ASTG + krow*KST + khalf; \
        const char* pkh = (const char*)(Kh + ((size_t)(b*S_ + (c)*64 + krow))*D_ + h*64) + khalf; \
        const char* pkl = (const char*)(Kl + ((size_t)(b*S_ + (c)*64 + krow))*D_ + h*64) + khalf; \
        const char* pvh = (const char*)(Vt + ((size_t)((b*H_+h)*64 + krow))*S_ + (c)*64) + khalf; \
        _Pragma("unroll") for (int i = 0; i < 4; i++) { \
            cpa16(dd + i*16,         pkh + i*16); \
            cpa16(dd + KPL + i*16,   pkl + i*16); \
            cpa16(dd + 2*KPL + i*16, pvh + i*16); } \
        asm volatile("cp.async.commit_group;" ::: "memory"); \
    } while (0)

    AISSUE(0, 0);
    const int NT = S_ / 64;
    for (int c = 0; c < NT; c++) {
        const int s = c & 1;
        if (c + 1 < NT) { AISSUE(c + 1, s ^ 1); asm volatile("cp.async.wait_group 1;" ::: "memory"); }
        else            { asm volatile("cp.async.wait_group 0;" ::: "memory"); }
        __syncthreads();
        const uint32_t base = sb + s * ASTG;
        const int brow = (lane & 7) + ((lane >> 4) << 3);
        const int bcsel = ((lane >> 3) & 1) << 4;

        uint2 mwa[2], mwb[2];
        #pragma unroll
        for (int mi = 0; mi < 2; mi++) {
            const uint32_t* mp = mb + (size_t)(q0 + w*32 + mi*16 + g) * (S_/32) + c*2;
            mwa[mi] = *(const uint2*)mp;
            mwb[mi] = *(const uint2*)(mp + 8 * (S_/32));
        }

        // ---- S = Q K^T (bf16, 3 split terms) ----
        float sacc[2][8][4] = {};
        #pragma unroll
        for (int kc = 0; kc < 4; kc++)
            #pragma unroll
            for (int np = 0; np < 4; np++) {
                uint32_t ad = base + (np*16 + brow) * KST + kc*32 + bcsel;
                uint32_t bh[4], bl[4];
                ldsm4(bh, ad); ldsm4(bl, ad + KPL);
                #pragma unroll
                for (int mi = 0; mi < 2; mi++) {
                    mmabf(sacc[mi][2*np],   qfh[mi][kc], bh[0], bh[1]);
                    mmabf(sacc[mi][2*np],   qfh[mi][kc], bl[0], bl[1]);
                    mmabf(sacc[mi][2*np],   qfl[mi][kc], bh[0], bh[1]);
                    mmabf(sacc[mi][2*np+1], qfh[mi][kc], bh[2], bh[3]);
                    mmabf(sacc[mi][2*np+1], qfh[mi][kc], bl[2], bl[3]);
                    mmabf(sacc[mi][2*np+1], qfl[mi][kc], bh[2], bh[3]);
                }
            }

        // ---- mask + online softmax (exp2 domain) ----
        #pragma unroll
        for (int mi = 0; mi < 2; mi++) {
            uint32_t allm = mwa[mi].x & mwa[mi].y & mwb[mi].x & mwb[mi].y;
            if (allm != 0xFFFFFFFFu) {
                #pragma unroll
                for (int nf = 0; nf < 8; nf++) {
                    uint32_t w0 = (nf < 4) ? mwa[mi].x : mwa[mi].y;
                    uint32_t w1 = (nf < 4) ? mwb[mi].x : mwb[mi].y;
                    int sh = qt*2 + (nf & 3)*8;
                    if (!((w0 >> sh) & 1))     sacc[mi][nf][0] = -1e9f;
                    if (!((w0 >> (sh+1)) & 1)) sacc[mi][nf][1] = -1e9f;
                    if (!((w1 >> sh) & 1))     sacc[mi][nf][2] = -1e9f;
                    if (!((w1 >> (sh+1)) & 1)) sacc[mi][nf][3] = -1e9f;
                }
            }
            float mx0 = -1e30f, mx1 = -1e30f;
            #pragma unroll
            for (int nf = 0; nf < 8; nf++) {
                mx0 = fmaxf(mx0, fmaxf(sacc[mi][nf][0], sacc[mi][nf][1]));
                mx1 = fmaxf(mx1, fmaxf(sacc[mi][nf][2], sacc[mi][nf][3]));
            }
            mx0 = fmaxf(mx0, __shfl_xor_sync(0xffffffffu, mx0, 1));
            mx0 = fmaxf(mx0, __shfl_xor_sync(0xffffffffu, mx0, 2));
            mx1 = fmaxf(mx1, __shfl_xor_sync(0xffffffffu, mx1, 1));
            mx1 = fmaxf(mx1, __shfl_xor_sync(0xffffffffu, mx1, 2));
            float mn0 = fmaxf(m_i[mi][0], mx0), mn1 = fmaxf(m_i[mi][1], mx1);
            float al0 = ex2(m_i[mi][0] - mn0), al1 = ex2(m_i[mi][1] - mn1);
            float s0 = 0.f, s1 = 0.f;
            #pragma unroll
            for (int nf = 0; nf < 8; nf++) {
                sacc[mi][nf][0] = ex2(sacc[mi][nf][0] - mn0);
                sacc[mi][nf][1] = ex2(sacc[mi][nf][1] - mn0);
                sacc[mi][nf][2] = ex2(sacc[mi][nf][2] - mn1);
                sacc[mi][nf][3] = ex2(sacc[mi][nf][3] - mn1);
                s0 += sacc[mi][nf][0] + sacc[mi][nf][1];
                s1 += sacc[mi][nf][2] + sacc[mi][nf][3];
            }
            s0 += __shfl_xor_sync(0xffffffffu, s0, 1);
            s0 += __shfl_xor_sync(0xffffffffu, s0, 2);
            s1 += __shfl_xor_sync(0xffffffffu, s1, 1);
            s1 += __shfl_xor_sync(0xffffffffu, s1, 2);
            l_i[mi][0] = l_i[mi][0]*al0 + s0; m_i[mi][0] = mn0;
            l_i[mi][1] = l_i[mi][1]*al1 + s1; m_i[mi][1] = mn1;
            #pragma unroll
            for (int nf = 0; nf < 8; nf++) {
                o[mi][nf][0] *= al0; o[mi][nf][1] *= al0;
                o[mi][nf][2] *= al1; o[mi][nf][3] *= al1;
            }
        }

        // ---- O += P V (fp16 single term) ----
        #pragma unroll
        for (int kc = 0; kc < 4; kc++) {
            uint32_t ph[2][4];
            #pragma unroll
            for (int mi = 0; mi < 2; mi++) {
                float* c0 = sacc[mi][2*kc];
                float* c1 = sacc[mi][2*kc+1];
                ph[mi][0] = pkh2(c0[0], c0[1]); ph[mi][1] = pkh2(c0[2], c0[3]);
                ph[mi][2] = pkh2(c1[0], c1[1]); ph[mi][3] = pkh2(c1[2], c1[3]);
            }
            #pragma unroll
            for (int np = 0; np < 4; np++) {
                uint32_t vd = base + 2*KPL + (np*16 + brow) * KST + kc*32 + bcsel;
                uint32_t vh[4];
                ldsm4(vh, vd);
                #pragma unroll
                for (int mi = 0; mi < 2; mi++) {
                    mmaf16(o[mi][2*np],   ph[mi], vh[0], vh[1]);
                    mmaf16(o[mi][2*np+1], ph[mi], vh[2], vh[3]);
                }
            }
        }
        __syncthreads();
    }
    #undef AISSUE

    #pragma unroll
    for (int mi = 0; mi < 2; mi++) {
        const int r0 = q0 + w*32 + mi*16 + g;
        const float i0 = 1.f / l_i[mi][0], i1 = 1.f / l_i[mi][1];
        #pragma unroll
        for (int nf = 0; nf < 8; nf++) {
            const int col = h*64 + nf*8 + qt*2;
            float v0 = o[mi][nf][0]*i0, v1 = o[mi][nf][1]*i0;
            float v2 = o[mi][nf][2]*i1, v3 = o[mi][nf][3]*i1;
            *(uint32_t*)&ctxh[(size_t)(b*S_ + r0)*D_ + col]     = pk2(v0, v1);
            *(uint32_t*)&ctxl[(size_t)(b*S_ + r0)*D_ + col]     = pk2(bflo(v0), bflo(v1));
            *(uint32_t*)&ctxh[(size_t)(b*S_ + r0 + 8)*D_ + col] = pk2(v2, v3);
            *(uint32_t*)&ctxl[(size_t)(b*S_ + r0 + 8)*D_ + col] = pk2(bflo(v2), bflo(v3));
        }
    }
}

// ---------------------------------------------------------------------------
extern "C" void kernel_launch(void* const* d_in, const int* in_sizes, int n_in,
                              void* d_out, int out_size)
{
    const float* q  = (const float*)d_in[0];
    const float* k  = (const float*)d_in[1];
    const float* v  = (const float*)d_in[2];
    const int* mask = (const int*)  d_in[3];
    const float* Wq = (const float*)d_in[4];  const float* bq = (const float*)d_in[5];
    const float* Wk = (const float*)d_in[6];  const float* bk = (const float*)d_in[7];
    const float* Wv = (const float*)d_in[8];  const float* bv = (const float*)d_in[9];
    const float* Wo = (const float*)d_in[10]; const float* bo = (const float*)d_in[11];
    float* out = (float*)d_out;

    float *Vp;
    __nv_bfloat16 *Ahp, *Alp, *Bhp, *Blp, *Qhp, *Qlp, *Khp, *Klp;
    __half* Vtp;
    uint32_t* mbp;
    cudaGetSymbolAddress((void**)&Vp, g_V);
    cudaGetSymbolAddress((void**)&Ahp, g_Ah); cudaGetSymbolAddress((void**)&Alp, g_Al);
    cudaGetSymbolAddress((void**)&Bhp, g_Bh); cudaGetSymbolAddress((void**)&Blp, g_Bl);
    cudaGetSymbolAddress((void**)&Qhp, g_Qh); cudaGetSymbolAddress((void**)&Qlp, g_Ql);
    cudaGetSymbolAddress((void**)&Khp, g_Kh); cudaGetSymbolAddress((void**)&Klp, g_Kl);
    cudaGetSymbolAddress((void**)&Vtp, g_Vt);
    cudaGetSymbolAddress((void**)&mbp, g_mb);

    const int MA4 = NACT / 4 / 256;
    const int MW4 = (D_ * D_) / 4 / 256;
    const float QSC = 0.125f * 1.44269504088896f;

    cudaFuncSetAttribute(gemm_qkv, cudaFuncAttributeMaxDynamicSharedMemorySize, GSM);
    cudaFuncSetAttribute(gemm_o,   cudaFuncAttributeMaxDynamicSharedMemorySize, GSM);
    cudaFuncSetAttribute(attn_mma, cudaFuncAttributeMaxDynamicSharedMemorySize, ASM);

    maskbits_kernel<<<(S_*S_)/256, 256>>>(mask, mbp);
    // slot stride in uint2 units: NACT bf16 per slot = NACT/4 uint2
    cvt3_kernel<<<dim3(MA4, 3), 256>>>(q, k, v, Ahp, Alp, NACT / 4);
    cvt4_kernel<<<dim3(MW4, 4), 256>>>(Wq, Wk, Wv, Wo, Bhp, Blp, (D_ * D_) / 4);

    gemm_qkv<<<dim3(D_/128, (B_*S_)/128, 3), 256, GSM>>>(
        Ahp, Alp, Bhp, Blp, bq, bk, bv, Vp, Qhp, Qlp, Khp, Klp, QSC);

    cvtT_kernel<<<dim3(S_/32, D_/32, B_), 256>>>(Vp, Vtp);

    attn_mma<<<dim3(S_/128, H_, B_), 128, ASM>>>(Qhp, Qlp, Khp, Klp, Vtp, mbp, Ahp, Alp);

    gemm_o<<<dim3(D_/128, (B_*S_)/128), 256, GSM>>>(
        Ahp, Alp, Bhp + (size_t)3*D_*D_, Blp + (size_t)3*D_*D_, bo, out);
}